// round 5
// baseline (speedup 1.0000x reference)
#include <cuda_runtime.h>
#include <math.h>
#include <stdint.h>

#define B_ 4
#define T_ 1024
#define D_ 1024
#define H_ 16
#define HD_ 64
#define BH_ 64
#define PAD 132

// ---------------- scratch (__device__ globals; no allocations allowed) -----
__device__ float g_h[B_*T_*D_];
__device__ float g_q[B_*T_*D_];
__device__ float g_k[B_*T_*D_];
__device__ float g_v[B_*T_*D_];
__device__ float g_ctx[B_*T_*D_];
__device__ float g_gate[BH_*T_];
__device__ float g_pb[H_*2048];
__device__ float2 g_stats[BH_*T_];
__device__ float g_scores[67108864];   // B*H*T*T fp32 = 256 MB

// ---------------- helpers ---------------------------------------------------
__device__ __forceinline__ float warp_sum(float v) {
    #pragma unroll
    for (int o = 16; o > 0; o >>= 1) v += __shfl_xor_sync(0xffffffffu, v, o);
    return v;
}
__device__ __forceinline__ float warp_max(float v) {
    #pragma unroll
    for (int o = 16; o > 0; o >>= 1) v = fmaxf(v, __shfl_xor_sync(0xffffffffu, v, o));
    return v;
}

// ---------------- LayerNorm: one block per row ------------------------------
__global__ void ln_kernel(const float* __restrict__ x, const float* __restrict__ w,
                          const float* __restrict__ bb, float* __restrict__ out)
{
    int row = blockIdx.x, tid = threadIdx.x;
    const float4* xr = (const float4*)(x + (size_t)row * D_);
    float4 v = xr[tid];
    float s  = v.x + v.y + v.z + v.w;
    float s2 = v.x*v.x + v.y*v.y + v.z*v.z + v.w*v.w;
    __shared__ float sm1[8], sm2[8];
    __shared__ float mu_s, inv_s;
    s = warp_sum(s); s2 = warp_sum(s2);
    if ((tid & 31) == 0) { sm1[tid >> 5] = s; sm2[tid >> 5] = s2; }
    __syncthreads();
    if (tid == 0) {
        float ts = 0.f, ts2 = 0.f;
        #pragma unroll
        for (int i = 0; i < 8; i++) { ts += sm1[i]; ts2 += sm2[i]; }
        float mu = ts / (float)D_;
        float var = ts2 / (float)D_ - mu * mu;
        mu_s = mu; inv_s = rsqrtf(var + 1e-5f);
    }
    __syncthreads();
    float mu = mu_s, inv = inv_s;
    float4 wv = ((const float4*)w)[tid];
    float4 bv = ((const float4*)bb)[tid];
    float4 o;
    o.x = (v.x - mu) * inv * wv.x + bv.x;
    o.y = (v.y - mu) * inv * wv.y + bv.y;
    o.z = (v.z - mu) * inv * wv.z + bv.z;
    o.w = (v.w - mu) * inv * wv.w + bv.w;
    ((float4*)(out + (size_t)row * D_))[tid] = o;
}

// ---------------- SGEMM NT, double-buffered, conflict-free fragments --------
// C = alpha*(A·B^T + bias) [+ resid].  A: MxK rm, B: NxK rm.  128x128x16.
// Thread tile: rows {ty*4..+3, 64+ty*4..+3} x cols {tx*4..+3, 64+tx*4..+3}.
__global__ void __launch_bounds__(256, 2) sgemm_nt_db(
    const float* __restrict__ A, const float* __restrict__ Bm,
    const float* __restrict__ bias, const float* __restrict__ resid,
    float alpha, float* __restrict__ C, int M, int N, int K)
{
    __shared__ float As[2][16][PAD];
    __shared__ float Bs[2][16][PAD];
    int tid = threadIdx.x;
    int bm = blockIdx.y * 128, bn = blockIdx.x * 128;
    int r0 = tid >> 2;             // 0..63
    int kc = (tid & 3) * 4;
    const float* Ap = A + (size_t)(bm + r0) * K + kc;
    const float* Bp = Bm + (size_t)(bn + r0) * K + kc;
    int tx = tid & 15, ty = tid >> 4;

    float acc[8][8] = {};
    float4 ra0, ra1, rb0, rb1;

    // prologue: tile 0
    ra0 = *(const float4*)(Ap);
    ra1 = *(const float4*)(Ap + (size_t)64 * K);
    rb0 = *(const float4*)(Bp);
    rb1 = *(const float4*)(Bp + (size_t)64 * K);
    #pragma unroll
    for (int j = 0; j < 4; j++) {
        As[0][kc+j][r0]    = ((float*)&ra0)[j];
        As[0][kc+j][r0+64] = ((float*)&ra1)[j];
        Bs[0][kc+j][r0]    = ((float*)&rb0)[j];
        Bs[0][kc+j][r0+64] = ((float*)&rb1)[j];
    }
    __syncthreads();

    int nkt = K >> 4;
    int buf = 0;
    for (int kt = 0; kt < nkt; ++kt) {
        if (kt + 1 < nkt) {
            const float* Ap2 = Ap + (kt + 1) * 16;
            const float* Bp2 = Bp + (kt + 1) * 16;
            ra0 = *(const float4*)(Ap2);
            ra1 = *(const float4*)(Ap2 + (size_t)64 * K);
            rb0 = *(const float4*)(Bp2);
            rb1 = *(const float4*)(Bp2 + (size_t)64 * K);
        }
        #pragma unroll
        for (int kk = 0; kk < 16; kk++) {
            float a[8], b[8];
            *(float4*)(a)   = *(const float4*)&As[buf][kk][ty*4];
            *(float4*)(a+4) = *(const float4*)&As[buf][kk][64 + ty*4];
            *(float4*)(b)   = *(const float4*)&Bs[buf][kk][tx*4];
            *(float4*)(b+4) = *(const float4*)&Bs[buf][kk][64 + tx*4];
            #pragma unroll
            for (int i = 0; i < 8; i++)
                #pragma unroll
                for (int j = 0; j < 8; j++) acc[i][j] += a[i] * b[j];
        }
        if (kt + 1 < nkt) {
            buf ^= 1;
            #pragma unroll
            for (int j = 0; j < 4; j++) {
                As[buf][kc+j][r0]    = ((float*)&ra0)[j];
                As[buf][kc+j][r0+64] = ((float*)&ra1)[j];
                Bs[buf][kc+j][r0]    = ((float*)&rb0)[j];
                Bs[buf][kc+j][r0+64] = ((float*)&rb1)[j];
            }
            __syncthreads();
        }
    }

    float4 blo = *(const float4*)&bias[bn + tx*4];
    float4 bhi = *(const float4*)&bias[bn + 64 + tx*4];
    #pragma unroll
    for (int i = 0; i < 8; i++) {
        int m = bm + ((i < 4) ? (ty*4 + i) : (64 + ty*4 + i - 4));
        float4 olo, ohi;
        olo.x = (acc[i][0] + blo.x) * alpha;
        olo.y = (acc[i][1] + blo.y) * alpha;
        olo.z = (acc[i][2] + blo.z) * alpha;
        olo.w = (acc[i][3] + blo.w) * alpha;
        ohi.x = (acc[i][4] + bhi.x) * alpha;
        ohi.y = (acc[i][5] + bhi.y) * alpha;
        ohi.z = (acc[i][6] + bhi.z) * alpha;
        ohi.w = (acc[i][7] + bhi.w) * alpha;
        if (resid) {
            float4 r1 = *(const float4*)&resid[(size_t)m * N + bn + tx*4];
            float4 r2 = *(const float4*)&resid[(size_t)m * N + bn + 64 + tx*4];
            olo.x += r1.x; olo.y += r1.y; olo.z += r1.z; olo.w += r1.w;
            ohi.x += r2.x; ohi.y += r2.y; ohi.z += r2.z; ohi.w += r2.w;
        }
        *(float4*)&C[(size_t)m * N + bn + tx*4]      = olo;
        *(float4*)&C[(size_t)m * N + bn + 64 + tx*4] = ohi;
    }
}

// ---------------- grep gate: one warp per (b,h,t) ---------------------------
__global__ void gate_kernel(const float* __restrict__ q, const float* __restrict__ gw,
                            const float* __restrict__ gb, const float* __restrict__ ga,
                            float* __restrict__ gate)
{
    __shared__ float sgw[8][64];
    int tid = threadIdx.x;
    ((float*)sgw)[tid]       = gw[tid];
    ((float*)sgw)[tid + 256] = gw[tid + 256];
    __syncthreads();
    int warp = tid >> 5, lane = tid & 31;
    size_t z = (size_t)blockIdx.x * 8 + warp;
    int t = (int)(z % T_);
    int h = (int)((z / T_) % H_);
    int b = (int)(z / ((size_t)H_ * T_));
    const float* qr = q + ((size_t)b * T_ + t) * D_ + h * HD_;
    float q0 = qr[lane] * 256.f;
    float q1 = qr[lane + 32] * 256.f;
    float y[8];
    #pragma unroll
    for (int j = 0; j < 8; j++)
        y[j] = q0 * sgw[j][lane] + q1 * sgw[j][lane + 32];
    #pragma unroll
    for (int o = 16; o > 0; o >>= 1)
        #pragma unroll
        for (int j = 0; j < 8; j++) y[j] += __shfl_xor_sync(0xffffffffu, y[j], o);
    if (lane == 0) {
        float s0 = y[0]+y[1]+y[2]+y[3] + gb[0]+gb[1]+gb[2]+gb[3];
        float s1 = y[4]+y[5]+y[6]+y[7] + gb[4]+gb[5]+gb[6]+gb[7];
        float ga_ = 1.f / (1.f + expf(-s0));
        float gbv = 1.f / (1.f + expf(-s1));
        gate[z] = ga_ * (gbv * ga[h] - 1.f) + 2.f;
    }
}

// ---------------- relative-position bias table: pb[h][rel+1023] -------------
__global__ void pbtable_kernel(const float* __restrict__ rel_emb, float* __restrict__ pb)
{
    int i = blockIdx.x * 256 + threadIdx.x;
    if (i >= 2048) return;
    if (i == 2047) {
        for (int h = 0; h < H_; h++) pb[h * 2048 + i] = 0.f;
        return;
    }
    int rel = i - 1023;
    int bucket = (rel > 0) ? 160 : 0;
    int n = abs(rel);
    int idx;
    if (n < 80) {
        idx = bucket + n;
    } else {
        double nf = (double)n;
        int large = 80 + (int)(log(nf / 80.0) / log(10.0) * 80.0);
        if (large > 159) large = 159;
        idx = bucket + large;
    }
    for (int h = 0; h < H_; h++) pb[h * 2048 + i] = rel_emb[idx * H_ + h];
}

// ---------------- pos_bias_out writer: (B*H, T, T) broadcast ----------------
__global__ void posbias_kernel(const float* __restrict__ pb, float* __restrict__ out)
{
    size_t gid = (size_t)blockIdx.x * 256 + threadIdx.x;
    int s4 = (int)(gid & 255);
    int t  = (int)((gid >> 8) & 1023);
    int bh = (int)(gid >> 18);
    int h  = bh & 15;
    const float* row = pb + h * 2048 + 1023 - t;
    int s = s4 * 4;
    float4 o = make_float4(row[s], row[s+1], row[s+2], row[s+3]);
    ((float4*)out)[gid] = o;
}

// ---------------- batched QK^T + gate*pb epilogue (db, conflict-free) -------
// grid (T/128, T/128, BH); K=64, lda=ldb=D_.
__global__ void __launch_bounds__(256, 2) qk_scores(
    const float* __restrict__ q, const float* __restrict__ k,
    const float* __restrict__ gate, const float* __restrict__ pb,
    float* __restrict__ scores)
{
    int z = blockIdx.z;
    int b = z / H_, h = z % H_;
    const float* A  = q + (size_t)b * T_ * D_ + h * HD_;
    const float* Bm = k + (size_t)b * T_ * D_ + h * HD_;
    float* C = scores + (size_t)z * T_ * T_;

    __shared__ float As[2][16][PAD];
    __shared__ float Bs[2][16][PAD];
    __shared__ float pbs[256];
    __shared__ float gs[128];

    int tid = threadIdx.x;
    int bm = blockIdx.y * 128, bn = blockIdx.x * 128;
    int base = bn - bm + 896;
    pbs[tid] = pb[h * 2048 + base + tid];
    if (tid < 128) gs[tid] = gate[(size_t)z * T_ + bm + tid];

    int r0 = tid >> 2;
    int kc = (tid & 3) * 4;
    const float* Ap = A + (size_t)(bm + r0) * D_ + kc;
    const float* Bp = Bm + (size_t)(bn + r0) * D_ + kc;
    int tx = tid & 15, ty = tid >> 4;

    float acc[8][8] = {};
    float4 ra0, ra1, rb0, rb1;

    ra0 = *(const float4*)(Ap);
    ra1 = *(const float4*)(Ap + (size_t)64 * D_);
    rb0 = *(const float4*)(Bp);
    rb1 = *(const float4*)(Bp + (size_t)64 * D_);
    #pragma unroll
    for (int j = 0; j < 4; j++) {
        As[0][kc+j][r0]    = ((float*)&ra0)[j];
        As[0][kc+j][r0+64] = ((float*)&ra1)[j];
        Bs[0][kc+j][r0]    = ((float*)&rb0)[j];
        Bs[0][kc+j][r0+64] = ((float*)&rb1)[j];
    }
    __syncthreads();

    int buf = 0;
    #pragma unroll
    for (int kt = 0; kt < 4; ++kt) {
        if (kt + 1 < 4) {
            const float* Ap2 = Ap + (kt + 1) * 16;
            const float* Bp2 = Bp + (kt + 1) * 16;
            ra0 = *(const float4*)(Ap2);
            ra1 = *(const float4*)(Ap2 + (size_t)64 * D_);
            rb0 = *(const float4*)(Bp2);
            rb1 = *(const float4*)(Bp2 + (size_t)64 * D_);
        }
        #pragma unroll
        for (int kk = 0; kk < 16; kk++) {
            float a[8], bb[8];
            *(float4*)(a)    = *(const float4*)&As[buf][kk][ty*4];
            *(float4*)(a+4)  = *(const float4*)&As[buf][kk][64 + ty*4];
            *(float4*)(bb)   = *(const float4*)&Bs[buf][kk][tx*4];
            *(float4*)(bb+4) = *(const float4*)&Bs[buf][kk][64 + tx*4];
            #pragma unroll
            for (int i = 0; i < 8; i++)
                #pragma unroll
                for (int j = 0; j < 8; j++) acc[i][j] += a[i] * bb[j];
        }
        if (kt + 1 < 4) {
            buf ^= 1;
            #pragma unroll
            for (int j = 0; j < 4; j++) {
                As[buf][kc+j][r0]    = ((float*)&ra0)[j];
                As[buf][kc+j][r0+64] = ((float*)&ra1)[j];
                Bs[buf][kc+j][r0]    = ((float*)&rb0)[j];
                Bs[buf][kc+j][r0+64] = ((float*)&rb1)[j];
            }
            __syncthreads();
        }
    }

    #pragma unroll
    for (int i = 0; i < 8; i++) {
        int mloc = (i < 4) ? (ty*4 + i) : (64 + ty*4 + i - 4);
        float gv = gs[mloc];
        float4 olo, ohi;
        {
            int n0 = tx*4;
            olo.x = acc[i][0] + gv * pbs[n0+0 - mloc + 127];
            olo.y = acc[i][1] + gv * pbs[n0+1 - mloc + 127];
            olo.z = acc[i][2] + gv * pbs[n0+2 - mloc + 127];
            olo.w = acc[i][3] + gv * pbs[n0+3 - mloc + 127];
            int n1 = 64 + tx*4;
            ohi.x = acc[i][4] + gv * pbs[n1+0 - mloc + 127];
            ohi.y = acc[i][5] + gv * pbs[n1+1 - mloc + 127];
            ohi.z = acc[i][6] + gv * pbs[n1+2 - mloc + 127];
            ohi.w = acc[i][7] + gv * pbs[n1+3 - mloc + 127];
        }
        *(float4*)&C[(size_t)(bm + mloc) * T_ + bn + tx*4]      = olo;
        *(float4*)&C[(size_t)(bm + mloc) * T_ + bn + 64 + tx*4] = ohi;
    }
}

// ---------------- softmax row stats: {max, 1/sum(exp)} ----------------------
__global__ void softmax_stats(const float* __restrict__ s, float2* __restrict__ stats)
{
    size_t row = blockIdx.x;
    const float4* p = (const float4*)(s + row * (size_t)T_);
    int tid = threadIdx.x;
    float4 v = p[tid];
    __shared__ float sm[8];
    __shared__ float bmax, bsum;
    float m = fmaxf(fmaxf(v.x, v.y), fmaxf(v.z, v.w));
    m = warp_max(m);
    if ((tid & 31) == 0) sm[tid >> 5] = m;
    __syncthreads();
    if (tid == 0) {
        float t = sm[0];
        #pragma unroll
        for (int i = 1; i < 8; i++) t = fmaxf(t, sm[i]);
        bmax = t;
    }
    __syncthreads();
    m = bmax;
    float su = __expf(v.x - m) + __expf(v.y - m) + __expf(v.z - m) + __expf(v.w - m);
    su = warp_sum(su);
    __syncthreads();
    if ((tid & 31) == 0) sm[tid >> 5] = su;
    __syncthreads();
    if (tid == 0) {
        float t = 0.f;
        #pragma unroll
        for (int i = 0; i < 8; i++) t += sm[i];
        bsum = t;
    }
    __syncthreads();
    if (tid == 0) stats[row] = make_float2(m, 1.f / bsum);
}

// ---------------- attn·V with fused softmax normalization -------------------
// ctx[t,d] = sum_s exp(sc[t,s]-m[t])*inv[t] * v[s,d].  BM=128,BN=64,BK=16, db.
__global__ void __launch_bounds__(256, 2) av_gemm(
    const float* __restrict__ sc, const float2* __restrict__ stats,
    const float* __restrict__ v, float* __restrict__ ctx)
{
    int z = blockIdx.z;
    int b = z / H_, h = z % H_;
    const float* A  = sc + (size_t)z * T_ * T_;              // lda = T
    const float* Bm = v + (size_t)b * T_ * D_ + h * HD_;     // ldb = D
    float* C = ctx + (size_t)b * T_ * D_ + h * HD_;          // ldc = D

    __shared__ float As[2][16][PAD];
    __shared__ float Bs[2][16][68];
    int tid = threadIdx.x;
    int bm = blockIdx.y * 128;
    int tx = tid & 15, ty = tid >> 4;
    int r0 = tid >> 2;              // 0..63 (A rows)
    int kc = (tid & 3) * 4;         // A k-chunk
    int bkr = tid >> 4;             // 0..15 (B k-row)
    int bcol = (tid & 15) * 4;      // B col

    float2 st0 = stats[(size_t)z * T_ + bm + r0];
    float2 st1 = stats[(size_t)z * T_ + bm + r0 + 64];

    const float* Ap = A + (size_t)(bm + r0) * T_ + kc;

    float acc[8][4] = {};
    float4 ra0, ra1, rb;

    // prologue
    ra0 = *(const float4*)(Ap);
    ra1 = *(const float4*)(Ap + (size_t)64 * T_);
    rb  = *(const float4*)(Bm + (size_t)bkr * D_ + bcol);
    {
        float4 e0, e1;
        e0.x = __expf(ra0.x - st0.x) * st0.y; e0.y = __expf(ra0.y - st0.x) * st0.y;
        e0.z = __expf(ra0.z - st0.x) * st0.y; e0.w = __expf(ra0.w - st0.x) * st0.y;
        e1.x = __expf(ra1.x - st1.x) * st1.y; e1.y = __expf(ra1.y - st1.x) * st1.y;
        e1.z = __expf(ra1.z - st1.x) * st1.y; e1.w = __expf(ra1.w - st1.x) * st1.y;
        #pragma unroll
        for (int j = 0; j < 4; j++) {
            As[0][kc+j][r0]    = ((float*)&e0)[j];
            As[0][kc+j][r0+64] = ((float*)&e1)[j];
        }
        *(float4*)&Bs[0][bkr][bcol] = rb;
    }
    __syncthreads();

    int buf = 0;
    for (int kt = 0; kt < 64; ++kt) {
        if (kt + 1 < 64) {
            ra0 = *(const float4*)(Ap + (kt + 1) * 16);
            ra1 = *(const float4*)(Ap + (kt + 1) * 16 + (size_t)64 * T_);
            rb  = *(const float4*)(Bm + (size_t)((kt + 1) * 16 + bkr) * D_ + bcol);
        }
        #pragma unroll
        for (int kk = 0; kk < 16; kk++) {
            float a[8], bb[4];
            *(float4*)(a)   = *(const float4*)&As[buf][kk][ty*4];
            *(float4*)(a+4) = *(const float4*)&As[buf][kk][64 + ty*4];
            *(float4*)(bb)  = *(const float4*)&Bs[buf][kk][tx*4];
            #pragma unroll
            for (int i = 0; i < 8; i++)
                #pragma unroll
                for (int j = 0; j < 4; j++) acc[i][j] += a[i] * bb[j];
        }
        if (kt + 1 < 64) {
            buf ^= 1;
            float4 e0, e1;
            e0.x = __expf(ra0.x - st0.x) * st0.y; e0.y = __expf(ra0.y - st0.x) * st0.y;
            e0.z = __expf(ra0.z - st0.x) * st0.y; e0.w = __expf(ra0.w - st0.x) * st0.y;
            e1.x = __expf(ra1.x - st1.x) * st1.y; e1.y = __expf(ra1.y - st1.x) * st1.y;
            e1.z = __expf(ra1.z - st1.x) * st1.y; e1.w = __expf(ra1.w - st1.x) * st1.y;
            #pragma unroll
            for (int j = 0; j < 4; j++) {
                As[buf][kc+j][r0]    = ((float*)&e0)[j];
                As[buf][kc+j][r0+64] = ((float*)&e1)[j];
            }
            *(float4*)&Bs[buf][bkr][bcol] = rb;
            __syncthreads();
        }
    }

    #pragma unroll
    for (int i = 0; i < 8; i++) {
        int mloc = (i < 4) ? (ty*4 + i) : (64 + ty*4 + i - 4);
        float4 o = make_float4(acc[i][0], acc[i][1], acc[i][2], acc[i][3]);
        *(float4*)&C[(size_t)(bm + mloc) * D_ + tx*4] = o;
    }
}

// ---------------- host launcher ---------------------------------------------
extern "C" void kernel_launch(void* const* d_in, const int* in_sizes, int n_in,
                              void* d_out, int out_size)
{
    const float* x      = (const float*)d_in[0];
    const float* ln_w   = (const float*)d_in[1];
    const float* ln_b   = (const float*)d_in[2];
    const float* wq     = (const float*)d_in[3];
    const float* bq     = (const float*)d_in[4];
    const float* wk     = (const float*)d_in[5];
    const float* bk     = (const float*)d_in[6];
    const float* wv     = (const float*)d_in[7];
    const float* bv     = (const float*)d_in[8];
    const float* wo     = (const float*)d_in[9];
    const float* bo     = (const float*)d_in[10];
    const float* rel_e  = (const float*)d_in[11];
    const float* grep_w = (const float*)d_in[12];
    const float* grep_b = (const float*)d_in[13];
    const float* grep_a = (const float*)d_in[14];

    float* out     = (float*)d_out;
    float* pos_out = out + (size_t)B_ * T_ * D_;

    float *p_h, *p_q, *p_k, *p_v, *p_ctx, *p_gate, *p_pb, *p_sc;
    float2* p_st;
    cudaGetSymbolAddress((void**)&p_h,    g_h);
    cudaGetSymbolAddress((void**)&p_q,    g_q);
    cudaGetSymbolAddress((void**)&p_k,    g_k);
    cudaGetSymbolAddress((void**)&p_v,    g_v);
    cudaGetSymbolAddress((void**)&p_ctx,  g_ctx);
    cudaGetSymbolAddress((void**)&p_gate, g_gate);
    cudaGetSymbolAddress((void**)&p_pb,   g_pb);
    cudaGetSymbolAddress((void**)&p_st,   g_stats);
    cudaGetSymbolAddress((void**)&p_sc,   g_scores);

    // 1. LayerNorm
    ln_kernel<<<B_*T_, 256>>>(x, ln_w, ln_b, p_h);

    // 2. QKV projections (NT GEMMs); q carries scaling = 64^-0.5
    dim3 g1(D_/128, (B_*T_)/128);
    sgemm_nt_db<<<g1, 256>>>(p_h, wq, bq, nullptr, 0.125f, p_q, B_*T_, D_, D_);
    sgemm_nt_db<<<g1, 256>>>(p_h, wk, bk, nullptr, 1.0f,   p_k, B_*T_, D_, D_);
    sgemm_nt_db<<<g1, 256>>>(p_h, wv, bv, nullptr, 1.0f,   p_v, B_*T_, D_, D_);

    // 3. grep gate
    gate_kernel<<<(BH_*T_)/8, 256>>>(p_q, grep_w, grep_b, grep_a, p_gate);

    // 4. rel-position bias table + broadcast output
    pbtable_kernel<<<8, 256>>>(rel_e, p_pb);
    posbias_kernel<<<65536, 256>>>(p_pb, pos_out);

    // 5. scores = q k^T + gate * pos_bias
    qk_scores<<<dim3(T_/128, T_/128, BH_), 256>>>(p_q, p_k, p_gate, p_pb, p_sc);

    // 6. softmax row stats only (normalization fused into av_gemm)
    softmax_stats<<<BH_*T_, 256>>>(p_sc, p_st);

    // 7. ctx = softmax(scores) @ v   (written directly in (B,T,D) layout)
    av_gemm<<<dim3(1, T_/128, BH_), 256>>>(p_sc, p_st, p_v, p_ctx);

    // 8. out = ctx @ wo^T + bo + x
    sgemm_nt_db<<<g1, 256>>>(p_ctx, wo, bo, x, 1.0f, out, B_*T_, D_, D_);
}

// round 6
// speedup vs baseline: 1.4025x; 1.4025x over previous
#include <cuda_runtime.h>
#include <math.h>
#include <stdint.h>

#define B_ 4
#define T_ 1024
#define D_ 1024
#define H_ 16
#define HD_ 64
#define BH_ 64
#define PAD 132

// XOR swizzle for tf32 smem tiles: makes transposed stores AND mma fragment
// loads bank-conflict-free with no padding.
#define SW(k) ((((k) ^ ((k) >> 2)) & 3) << 3)

// ---------------- scratch (__device__ globals; no allocations allowed) -----
__device__ float g_h[B_*T_*D_];
__device__ float g_q[B_*T_*D_];
__device__ float g_k[B_*T_*D_];
__device__ float g_v[B_*T_*D_];
__device__ float g_ctx[B_*T_*D_];
__device__ float g_gate[BH_*T_];
__device__ float g_pb[H_*2048];
__device__ float2 g_stats[BH_*T_];
__device__ float g_scores[67108864];   // B*H*T*T fp32 = 256 MB

// ---------------- helpers ---------------------------------------------------
__device__ __forceinline__ float warp_sum(float v) {
    #pragma unroll
    for (int o = 16; o > 0; o >>= 1) v += __shfl_xor_sync(0xffffffffu, v, o);
    return v;
}
__device__ __forceinline__ float warp_max(float v) {
    #pragma unroll
    for (int o = 16; o > 0; o >>= 1) v = fmaxf(v, __shfl_xor_sync(0xffffffffu, v, o));
    return v;
}
__device__ __forceinline__ uint32_t f2tf32(float f) {
    uint32_t u;
    asm("cvt.rna.tf32.f32 %0, %1;" : "=r"(u) : "f"(f));
    return u;
}
__device__ __forceinline__ void mma_tf32(float* c, const uint32_t* a, const uint32_t* b) {
    asm volatile(
        "mma.sync.aligned.m16n8k8.row.col.f32.tf32.tf32.f32 "
        "{%0,%1,%2,%3}, {%4,%5,%6,%7}, {%8,%9}, {%0,%1,%2,%3};\n"
        : "+f"(c[0]), "+f"(c[1]), "+f"(c[2]), "+f"(c[3])
        : "r"(a[0]), "r"(a[1]), "r"(a[2]), "r"(a[3]), "r"(b[0]), "r"(b[1]));
}

// ---------------- LayerNorm: one block per row ------------------------------
__global__ void ln_kernel(const float* __restrict__ x, const float* __restrict__ w,
                          const float* __restrict__ bb, float* __restrict__ out)
{
    int row = blockIdx.x, tid = threadIdx.x;
    const float4* xr = (const float4*)(x + (size_t)row * D_);
    float4 v = xr[tid];
    float s  = v.x + v.y + v.z + v.w;
    float s2 = v.x*v.x + v.y*v.y + v.z*v.z + v.w*v.w;
    __shared__ float sm1[8], sm2[8];
    __shared__ float mu_s, inv_s;
    s = warp_sum(s); s2 = warp_sum(s2);
    if ((tid & 31) == 0) { sm1[tid >> 5] = s; sm2[tid >> 5] = s2; }
    __syncthreads();
    if (tid == 0) {
        float ts = 0.f, ts2 = 0.f;
        #pragma unroll
        for (int i = 0; i < 8; i++) { ts += sm1[i]; ts2 += sm2[i]; }
        float mu = ts / (float)D_;
        float var = ts2 / (float)D_ - mu * mu;
        mu_s = mu; inv_s = rsqrtf(var + 1e-5f);
    }
    __syncthreads();
    float mu = mu_s, inv = inv_s;
    float4 wv = ((const float4*)w)[tid];
    float4 bv = ((const float4*)bb)[tid];
    float4 o;
    o.x = (v.x - mu) * inv * wv.x + bv.x;
    o.y = (v.y - mu) * inv * wv.y + bv.y;
    o.z = (v.z - mu) * inv * wv.z + bv.z;
    o.w = (v.w - mu) * inv * wv.w + bv.w;
    ((float4*)(out + (size_t)row * D_))[tid] = o;
}

// ---------------- tf32 tensor-core GEMM NT ----------------------------------
// C = alpha*(A·B^T + bias) [+ resid].  A: MxK rm, B: NxK rm. 128x128x16,
// 8 warps (2x4), warp tile 64x32 via mma.sync m16n8k8 tf32, double-buffered.
__global__ void __launch_bounds__(256, 2) sgemm_tf32(
    const float* __restrict__ A, const float* __restrict__ Bm,
    const float* __restrict__ bias, const float* __restrict__ resid,
    float alpha, float* __restrict__ C, int M, int N, int K)
{
    __shared__ uint32_t As[2][16][128];
    __shared__ uint32_t Bs[2][16][128];
    int tid = threadIdx.x;
    int bm = blockIdx.y * 128, bn = blockIdx.x * 128;
    int r0 = tid >> 2;              // 0..63
    int kc = (tid & 3) * 4;
    const float* Ap = A + (size_t)(bm + r0) * K + kc;
    const float* Bp = Bm + (size_t)(bn + r0) * K + kc;

    int warp = tid >> 5, lane = tid & 31;
    int mw = (warp >> 2) * 64;      // warp row base
    int nw = (warp & 3) * 32;       // warp col base
    int gr = lane >> 2, c4 = lane & 3;

    float acc[4][4][4];
    #pragma unroll
    for (int i = 0; i < 4; i++)
        #pragma unroll
        for (int j = 0; j < 4; j++)
            #pragma unroll
            for (int l = 0; l < 4; l++) acc[i][j][l] = 0.f;

    float4 ra0, ra1, rb0, rb1;

    // prologue: tile 0
    ra0 = *(const float4*)(Ap);
    ra1 = *(const float4*)(Ap + (size_t)64 * K);
    rb0 = *(const float4*)(Bp);
    rb1 = *(const float4*)(Bp + (size_t)64 * K);
    #pragma unroll
    for (int j = 0; j < 4; j++) {
        int k = kc + j, sw = SW(k);
        As[0][k][r0 ^ sw]        = f2tf32(((float*)&ra0)[j]);
        As[0][k][(r0 + 64) ^ sw] = f2tf32(((float*)&ra1)[j]);
        Bs[0][k][r0 ^ sw]        = f2tf32(((float*)&rb0)[j]);
        Bs[0][k][(r0 + 64) ^ sw] = f2tf32(((float*)&rb1)[j]);
    }
    __syncthreads();

    int nkt = K >> 4;
    int buf = 0;
    for (int kt = 0; kt < nkt; ++kt) {
        if (kt + 1 < nkt) {
            const float* Ap2 = Ap + (kt + 1) * 16;
            const float* Bp2 = Bp + (kt + 1) * 16;
            ra0 = *(const float4*)(Ap2);
            ra1 = *(const float4*)(Ap2 + (size_t)64 * K);
            rb0 = *(const float4*)(Bp2);
            rb1 = *(const float4*)(Bp2 + (size_t)64 * K);
        }
        #pragma unroll
        for (int ks = 0; ks < 16; ks += 8) {
            int k0 = ks + c4, k1 = ks + c4 + 4;
            int s0 = SW(k0), s1 = SW(k1);
            uint32_t af[4][4], bfr[4][2];
            #pragma unroll
            for (int mi = 0; mi < 4; mi++) {
                int m = mw + mi * 16 + gr;
                af[mi][0] = As[buf][k0][m ^ s0];
                af[mi][1] = As[buf][k0][(m + 8) ^ s0];
                af[mi][2] = As[buf][k1][m ^ s1];
                af[mi][3] = As[buf][k1][(m + 8) ^ s1];
            }
            #pragma unroll
            for (int ni = 0; ni < 4; ni++) {
                int n = nw + ni * 8 + gr;
                bfr[ni][0] = Bs[buf][k0][n ^ s0];
                bfr[ni][1] = Bs[buf][k1][n ^ s1];
            }
            #pragma unroll
            for (int mi = 0; mi < 4; mi++)
                #pragma unroll
                for (int ni = 0; ni < 4; ni++)
                    mma_tf32(acc[mi][ni], af[mi], bfr[ni]);
        }
        if (kt + 1 < nkt) {
            buf ^= 1;
            #pragma unroll
            for (int j = 0; j < 4; j++) {
                int k = kc + j, sw = SW(k);
                As[buf][k][r0 ^ sw]        = f2tf32(((float*)&ra0)[j]);
                As[buf][k][(r0 + 64) ^ sw] = f2tf32(((float*)&ra1)[j]);
                Bs[buf][k][r0 ^ sw]        = f2tf32(((float*)&rb0)[j]);
                Bs[buf][k][(r0 + 64) ^ sw] = f2tf32(((float*)&rb1)[j]);
            }
            __syncthreads();
        }
    }

    // epilogue
    #pragma unroll
    for (int ni = 0; ni < 4; ni++) {
        int ng = bn + nw + ni * 8 + c4 * 2;
        float2 b2 = *(const float2*)&bias[ng];
        #pragma unroll
        for (int mi = 0; mi < 4; mi++) {
            int mg = bm + mw + mi * 16 + gr;
            float2 lo, hi;
            lo.x = (acc[mi][ni][0] + b2.x) * alpha;
            lo.y = (acc[mi][ni][1] + b2.y) * alpha;
            hi.x = (acc[mi][ni][2] + b2.x) * alpha;
            hi.y = (acc[mi][ni][3] + b2.y) * alpha;
            if (resid) {
                float2 r1 = *(const float2*)&resid[(size_t)mg * N + ng];
                float2 r2 = *(const float2*)&resid[(size_t)(mg + 8) * N + ng];
                lo.x += r1.x; lo.y += r1.y;
                hi.x += r2.x; hi.y += r2.y;
            }
            *(float2*)&C[(size_t)mg * N + ng]       = lo;
            *(float2*)&C[(size_t)(mg + 8) * N + ng] = hi;
        }
    }
}

// ---------------- grep gate: one warp per (b,h,t) ---------------------------
__global__ void gate_kernel(const float* __restrict__ q, const float* __restrict__ gw,
                            const float* __restrict__ gb, const float* __restrict__ ga,
                            float* __restrict__ gate)
{
    __shared__ float sgw[8][64];
    int tid = threadIdx.x;
    ((float*)sgw)[tid]       = gw[tid];
    ((float*)sgw)[tid + 256] = gw[tid + 256];
    __syncthreads();
    int warp = tid >> 5, lane = tid & 31;
    size_t z = (size_t)blockIdx.x * 8 + warp;
    int t = (int)(z % T_);
    int h = (int)((z / T_) % H_);
    int b = (int)(z / ((size_t)H_ * T_));
    const float* qr = q + ((size_t)b * T_ + t) * D_ + h * HD_;
    float q0 = qr[lane] * 256.f;
    float q1 = qr[lane + 32] * 256.f;
    float y[8];
    #pragma unroll
    for (int j = 0; j < 8; j++)
        y[j] = q0 * sgw[j][lane] + q1 * sgw[j][lane + 32];
    #pragma unroll
    for (int o = 16; o > 0; o >>= 1)
        #pragma unroll
        for (int j = 0; j < 8; j++) y[j] += __shfl_xor_sync(0xffffffffu, y[j], o);
    if (lane == 0) {
        float s0 = y[0]+y[1]+y[2]+y[3] + gb[0]+gb[1]+gb[2]+gb[3];
        float s1 = y[4]+y[5]+y[6]+y[7] + gb[4]+gb[5]+gb[6]+gb[7];
        float ga_ = 1.f / (1.f + expf(-s0));
        float gbv = 1.f / (1.f + expf(-s1));
        gate[z] = ga_ * (gbv * ga[h] - 1.f) + 2.f;
    }
}

// ---------------- relative-position bias table: pb[h][rel+1023] -------------
__global__ void pbtable_kernel(const float* __restrict__ rel_emb, float* __restrict__ pb)
{
    int i = blockIdx.x * 256 + threadIdx.x;
    if (i >= 2048) return;
    if (i == 2047) {
        for (int h = 0; h < H_; h++) pb[h * 2048 + i] = 0.f;
        return;
    }
    int rel = i - 1023;
    int bucket = (rel > 0) ? 160 : 0;
    int n = abs(rel);
    int idx;
    if (n < 80) {
        idx = bucket + n;
    } else {
        double nf = (double)n;
        int large = 80 + (int)(log(nf / 80.0) / log(10.0) * 80.0);
        if (large > 159) large = 159;
        idx = bucket + large;
    }
    for (int h = 0; h < H_; h++) pb[h * 2048 + i] = rel_emb[idx * H_ + h];
}

// ---------------- pos_bias_out writer: (B*H, T, T) broadcast ----------------
__global__ void posbias_kernel(const float* __restrict__ pb, float* __restrict__ out)
{
    size_t gid = (size_t)blockIdx.x * 256 + threadIdx.x;
    int s4 = (int)(gid & 255);
    int t  = (int)((gid >> 8) & 1023);
    int bh = (int)(gid >> 18);
    int h  = bh & 15;
    const float* row = pb + h * 2048 + 1023 - t;
    int s = s4 * 4;
    float4 o = make_float4(row[s], row[s+1], row[s+2], row[s+3]);
    ((float4*)out)[gid] = o;
}

// ---------------- batched QK^T + gate*pb epilogue (db, conflict-free) -------
// grid (T/128, T/128, BH); K=64, lda=ldb=D_.
__global__ void __launch_bounds__(256, 2) qk_scores(
    const float* __restrict__ q, const float* __restrict__ k,
    const float* __restrict__ gate, const float* __restrict__ pb,
    float* __restrict__ scores)
{
    int z = blockIdx.z;
    int b = z / H_, h = z % H_;
    const float* A  = q + (size_t)b * T_ * D_ + h * HD_;
    const float* Bm = k + (size_t)b * T_ * D_ + h * HD_;
    float* C = scores + (size_t)z * T_ * T_;

    __shared__ float As[2][16][PAD];
    __shared__ float Bs[2][16][PAD];
    __shared__ float pbs[256];
    __shared__ float gs[128];

    int tid = threadIdx.x;
    int bm = blockIdx.y * 128, bn = blockIdx.x * 128;
    int base = bn - bm + 896;
    pbs[tid] = pb[h * 2048 + base + tid];
    if (tid < 128) gs[tid] = gate[(size_t)z * T_ + bm + tid];

    int r0 = tid >> 2;
    int kc = (tid & 3) * 4;
    const float* Ap = A + (size_t)(bm + r0) * D_ + kc;
    const float* Bp = Bm + (size_t)(bn + r0) * D_ + kc;
    int tx = tid & 15, ty = tid >> 4;

    float acc[8][8] = {};
    float4 ra0, ra1, rb0, rb1;

    ra0 = *(const float4*)(Ap);
    ra1 = *(const float4*)(Ap + (size_t)64 * D_);
    rb0 = *(const float4*)(Bp);
    rb1 = *(const float4*)(Bp + (size_t)64 * D_);
    #pragma unroll
    for (int j = 0; j < 4; j++) {
        As[0][kc+j][r0]    = ((float*)&ra0)[j];
        As[0][kc+j][r0+64] = ((float*)&ra1)[j];
        Bs[0][kc+j][r0]    = ((float*)&rb0)[j];
        Bs[0][kc+j][r0+64] = ((float*)&rb1)[j];
    }
    __syncthreads();

    int buf = 0;
    #pragma unroll
    for (int kt = 0; kt < 4; ++kt) {
        if (kt + 1 < 4) {
            const float* Ap2 = Ap + (kt + 1) * 16;
            const float* Bp2 = Bp + (kt + 1) * 16;
            ra0 = *(const float4*)(Ap2);
            ra1 = *(const float4*)(Ap2 + (size_t)64 * D_);
            rb0 = *(const float4*)(Bp2);
            rb1 = *(const float4*)(Bp2 + (size_t)64 * D_);
        }
        #pragma unroll
        for (int kk = 0; kk < 16; kk++) {
            float a[8], bb[8];
            *(float4*)(a)    = *(const float4*)&As[buf][kk][ty*4];
            *(float4*)(a+4)  = *(const float4*)&As[buf][kk][64 + ty*4];
            *(float4*)(bb)   = *(const float4*)&Bs[buf][kk][tx*4];
            *(float4*)(bb+4) = *(const float4*)&Bs[buf][kk][64 + tx*4];
            #pragma unroll
            for (int i = 0; i < 8; i++)
                #pragma unroll
                for (int j = 0; j < 8; j++) acc[i][j] += a[i] * bb[j];
        }
        if (kt + 1 < 4) {
            buf ^= 1;
            #pragma unroll
            for (int j = 0; j < 4; j++) {
                As[buf][kc+j][r0]    = ((float*)&ra0)[j];
                As[buf][kc+j][r0+64] = ((float*)&ra1)[j];
                Bs[buf][kc+j][r0]    = ((float*)&rb0)[j];
                Bs[buf][kc+j][r0+64] = ((float*)&rb1)[j];
            }
            __syncthreads();
        }
    }

    #pragma unroll
    for (int i = 0; i < 8; i++) {
        int mloc = (i < 4) ? (ty*4 + i) : (64 + ty*4 + i - 4);
        float gv = gs[mloc];
        float4 olo, ohi;
        {
            int n0 = tx*4;
            olo.x = acc[i][0] + gv * pbs[n0+0 - mloc + 127];
            olo.y = acc[i][1] + gv * pbs[n0+1 - mloc + 127];
            olo.z = acc[i][2] + gv * pbs[n0+2 - mloc + 127];
            olo.w = acc[i][3] + gv * pbs[n0+3 - mloc + 127];
            int n1 = 64 + tx*4;
            ohi.x = acc[i][4] + gv * pbs[n1+0 - mloc + 127];
            ohi.y = acc[i][5] + gv * pbs[n1+1 - mloc + 127];
            ohi.z = acc[i][6] + gv * pbs[n1+2 - mloc + 127];
            ohi.w = acc[i][7] + gv * pbs[n1+3 - mloc + 127];
        }
        *(float4*)&C[(size_t)(bm + mloc) * T_ + bn + tx*4]      = olo;
        *(float4*)&C[(size_t)(bm + mloc) * T_ + bn + 64 + tx*4] = ohi;
    }
}

// ---------------- softmax row stats: {max, 1/sum(exp)} ----------------------
__global__ void softmax_stats(const float* __restrict__ s, float2* __restrict__ stats)
{
    size_t row = blockIdx.x;
    const float4* p = (const float4*)(s + row * (size_t)T_);
    int tid = threadIdx.x;
    float4 v = p[tid];
    __shared__ float sm[8];
    __shared__ float bmax, bsum;
    float m = fmaxf(fmaxf(v.x, v.y), fmaxf(v.z, v.w));
    m = warp_max(m);
    if ((tid & 31) == 0) sm[tid >> 5] = m;
    __syncthreads();
    if (tid == 0) {
        float t = sm[0];
        #pragma unroll
        for (int i = 1; i < 8; i++) t = fmaxf(t, sm[i]);
        bmax = t;
    }
    __syncthreads();
    m = bmax;
    float su = __expf(v.x - m) + __expf(v.y - m) + __expf(v.z - m) + __expf(v.w - m);
    su = warp_sum(su);
    __syncthreads();
    if ((tid & 31) == 0) sm[tid >> 5] = su;
    __syncthreads();
    if (tid == 0) {
        float t = 0.f;
        #pragma unroll
        for (int i = 0; i < 8; i++) t += sm[i];
        bsum = t;
    }
    __syncthreads();
    if (tid == 0) stats[row] = make_float2(m, 1.f / bsum);
}

// ---------------- attn·V with fused softmax normalization -------------------
// ctx[t,d] = sum_s exp(sc[t,s]-m[t])*inv[t] * v[s,d].  BM=128,BN=64,BK=16, db.
__global__ void __launch_bounds__(256, 2) av_gemm(
    const float* __restrict__ sc, const float2* __restrict__ stats,
    const float* __restrict__ v, float* __restrict__ ctx)
{
    int z = blockIdx.z;
    int b = z / H_, h = z % H_;
    const float* A  = sc + (size_t)z * T_ * T_;              // lda = T
    const float* Bm = v + (size_t)b * T_ * D_ + h * HD_;     // ldb = D
    float* C = ctx + (size_t)b * T_ * D_ + h * HD_;          // ldc = D

    __shared__ float As[2][16][PAD];
    __shared__ float Bs[2][16][68];
    int tid = threadIdx.x;
    int bm = blockIdx.y * 128;
    int tx = tid & 15, ty = tid >> 4;
    int r0 = tid >> 2;
    int kc = (tid & 3) * 4;
    int bkr = tid >> 4;
    int bcol = (tid & 15) * 4;

    float2 st0 = stats[(size_t)z * T_ + bm + r0];
    float2 st1 = stats[(size_t)z * T_ + bm + r0 + 64];

    const float* Ap = A + (size_t)(bm + r0) * T_ + kc;

    float acc[8][4] = {};
    float4 ra0, ra1, rb;

    ra0 = *(const float4*)(Ap);
    ra1 = *(const float4*)(Ap + (size_t)64 * T_);
    rb  = *(const float4*)(Bm + (size_t)bkr * D_ + bcol);
    {
        float4 e0, e1;
        e0.x = __expf(ra0.x - st0.x) * st0.y; e0.y = __expf(ra0.y - st0.x) * st0.y;
        e0.z = __expf(ra0.z - st0.x) * st0.y; e0.w = __expf(ra0.w - st0.x) * st0.y;
        e1.x = __expf(ra1.x - st1.x) * st1.y; e1.y = __expf(ra1.y - st1.x) * st1.y;
        e1.z = __expf(ra1.z - st1.x) * st1.y; e1.w = __expf(ra1.w - st1.x) * st1.y;
        #pragma unroll
        for (int j = 0; j < 4; j++) {
            As[0][kc+j][r0]    = ((float*)&e0)[j];
            As[0][kc+j][r0+64] = ((float*)&e1)[j];
        }
        *(float4*)&Bs[0][bkr][bcol] = rb;
    }
    __syncthreads();

    int buf = 0;
    for (int kt = 0; kt < 64; ++kt) {
        if (kt + 1 < 64) {
            ra0 = *(const float4*)(Ap + (kt + 1) * 16);
            ra1 = *(const float4*)(Ap + (kt + 1) * 16 + (size_t)64 * T_);
            rb  = *(const float4*)(Bm + (size_t)((kt + 1) * 16 + bkr) * D_ + bcol);
        }
        #pragma unroll
        for (int kk = 0; kk < 16; kk++) {
            float a[8], bb[4];
            *(float4*)(a)   = *(const float4*)&As[buf][kk][ty*4];
            *(float4*)(a+4) = *(const float4*)&As[buf][kk][64 + ty*4];
            *(float4*)(bb)  = *(const float4*)&Bs[buf][kk][tx*4];
            #pragma unroll
            for (int i = 0; i < 8; i++)
                #pragma unroll
                for (int j = 0; j < 4; j++) acc[i][j] += a[i] * bb[j];
        }
        if (kt + 1 < 64) {
            buf ^= 1;
            float4 e0, e1;
            e0.x = __expf(ra0.x - st0.x) * st0.y; e0.y = __expf(ra0.y - st0.x) * st0.y;
            e0.z = __expf(ra0.z - st0.x) * st0.y; e0.w = __expf(ra0.w - st0.x) * st0.y;
            e1.x = __expf(ra1.x - st1.x) * st1.y; e1.y = __expf(ra1.y - st1.x) * st1.y;
            e1.z = __expf(ra1.z - st1.x) * st1.y; e1.w = __expf(ra1.w - st1.x) * st1.y;
            #pragma unroll
            for (int j = 0; j < 4; j++) {
                As[buf][kc+j][r0]    = ((float*)&e0)[j];
                As[buf][kc+j][r0+64] = ((float*)&e1)[j];
            }
            *(float4*)&Bs[buf][bkr][bcol] = rb;
            __syncthreads();
        }
    }

    #pragma unroll
    for (int i = 0; i < 8; i++) {
        int mloc = (i < 4) ? (ty*4 + i) : (64 + ty*4 + i - 4);
        float4 o = make_float4(acc[i][0], acc[i][1], acc[i][2], acc[i][3]);
        *(float4*)&C[(size_t)(bm + mloc) * D_ + tx*4] = o;
    }
}

// ---------------- host launcher ---------------------------------------------
extern "C" void kernel_launch(void* const* d_in, const int* in_sizes, int n_in,
                              void* d_out, int out_size)
{
    const float* x      = (const float*)d_in[0];
    const float* ln_w   = (const float*)d_in[1];
    const float* ln_b   = (const float*)d_in[2];
    const float* wq     = (const float*)d_in[3];
    const float* bq     = (const float*)d_in[4];
    const float* wk     = (const float*)d_in[5];
    const float* bk     = (const float*)d_in[6];
    const float* wv     = (const float*)d_in[7];
    const float* bv     = (const float*)d_in[8];
    const float* wo     = (const float*)d_in[9];
    const float* bo     = (const float*)d_in[10];
    const float* rel_e  = (const float*)d_in[11];
    const float* grep_w = (const float*)d_in[12];
    const float* grep_b = (const float*)d_in[13];
    const float* grep_a = (const float*)d_in[14];

    float* out     = (float*)d_out;
    float* pos_out = out + (size_t)B_ * T_ * D_;

    float *p_h, *p_q, *p_k, *p_v, *p_ctx, *p_gate, *p_pb, *p_sc;
    float2* p_st;
    cudaGetSymbolAddress((void**)&p_h,    g_h);
    cudaGetSymbolAddress((void**)&p_q,    g_q);
    cudaGetSymbolAddress((void**)&p_k,    g_k);
    cudaGetSymbolAddress((void**)&p_v,    g_v);
    cudaGetSymbolAddress((void**)&p_ctx,  g_ctx);
    cudaGetSymbolAddress((void**)&p_gate, g_gate);
    cudaGetSymbolAddress((void**)&p_pb,   g_pb);
    cudaGetSymbolAddress((void**)&p_st,   g_stats);
    cudaGetSymbolAddress((void**)&p_sc,   g_scores);

    // 1. LayerNorm
    ln_kernel<<<B_*T_, 256>>>(x, ln_w, ln_b, p_h);

    // 2. QKV projections (tf32 tensor-core NT GEMMs); q carries 64^-0.5
    dim3 g1(D_/128, (B_*T_)/128);
    sgemm_tf32<<<g1, 256>>>(p_h, wq, bq, nullptr, 0.125f, p_q, B_*T_, D_, D_);
    sgemm_tf32<<<g1, 256>>>(p_h, wk, bk, nullptr, 1.0f,   p_k, B_*T_, D_, D_);
    sgemm_tf32<<<g1, 256>>>(p_h, wv, bv, nullptr, 1.0f,   p_v, B_*T_, D_, D_);

    // 3. grep gate
    gate_kernel<<<(BH_*T_)/8, 256>>>(p_q, grep_w, grep_b, grep_a, p_gate);

    // 4. rel-position bias table + broadcast output
    pbtable_kernel<<<8, 256>>>(rel_e, p_pb);
    posbias_kernel<<<65536, 256>>>(p_pb, pos_out);

    // 5. scores = q k^T + gate * pos_bias
    qk_scores<<<dim3(T_/128, T_/128, BH_), 256>>>(p_q, p_k, p_gate, p_pb, p_sc);

    // 6. softmax row stats only (normalization fused into av_gemm)
    softmax_stats<<<BH_*T_, 256>>>(p_sc, p_st);

    // 7. ctx = softmax(scores) @ v   (written directly in (B,T,D) layout)
    av_gemm<<<dim3(1, T_/128, BH_), 256>>>(p_sc, p_st, p_v, p_ctx);

    // 8. out = ctx @ wo^T + bo + x
    sgemm_tf32<<<g1, 256>>>(p_ctx, wo, bo, x, 1.0f, out, B_*T_, D_, D_);
}

// round 7
// speedup vs baseline: 1.5463x; 1.1025x over previous
#include <cuda_runtime.h>
#include <math.h>
#include <stdint.h>

#define B_ 4
#define T_ 1024
#define D_ 1024
#define H_ 16
#define HD_ 64
#define BH_ 64

// XOR swizzle for tf32 smem tiles (width-128 rows): conflict-free transposed
// stores + mma fragment loads, no padding.
#define SW(k) ((((k) ^ ((k) >> 2)) & 3) << 3)
// swizzle for width-64 rows (V tile): 4 k-rows per bank group
#define SWB(k) (((k) & 3) << 3)

// ---------------- scratch (__device__ globals; no allocations allowed) -----
__device__ float g_h[B_*T_*D_];
__device__ float g_q[B_*T_*D_];
__device__ float g_k[B_*T_*D_];
__device__ float g_v[B_*T_*D_];
__device__ float g_ctx[B_*T_*D_];
__device__ float g_gate[BH_*T_];
__device__ float g_pb[H_*2048];
__device__ float2 g_stats[BH_*T_];
__device__ float g_scores[67108864];   // B*H*T*T fp32 = 256 MB

// ---------------- helpers ---------------------------------------------------
__device__ __forceinline__ float warp_sum(float v) {
    #pragma unroll
    for (int o = 16; o > 0; o >>= 1) v += __shfl_xor_sync(0xffffffffu, v, o);
    return v;
}
__device__ __forceinline__ float warp_max(float v) {
    #pragma unroll
    for (int o = 16; o > 0; o >>= 1) v = fmaxf(v, __shfl_xor_sync(0xffffffffu, v, o));
    return v;
}
__device__ __forceinline__ uint32_t f2tf32(float f) {
    uint32_t u;
    asm("cvt.rna.tf32.f32 %0, %1;" : "=r"(u) : "f"(f));
    return u;
}
__device__ __forceinline__ void mma_tf32(float* c, const uint32_t* a, const uint32_t* b) {
    asm volatile(
        "mma.sync.aligned.m16n8k8.row.col.f32.tf32.tf32.f32 "
        "{%0,%1,%2,%3}, {%4,%5,%6,%7}, {%8,%9}, {%0,%1,%2,%3};\n"
        : "+f"(c[0]), "+f"(c[1]), "+f"(c[2]), "+f"(c[3])
        : "r"(a[0]), "r"(a[1]), "r"(a[2]), "r"(a[3]), "r"(b[0]), "r"(b[1]));
}

// ---------------- LayerNorm: one block per row ------------------------------
__global__ void ln_kernel(const float* __restrict__ x, const float* __restrict__ w,
                          const float* __restrict__ bb, float* __restrict__ out)
{
    int row = blockIdx.x, tid = threadIdx.x;
    const float4* xr = (const float4*)(x + (size_t)row * D_);
    float4 v = xr[tid];
    float s  = v.x + v.y + v.z + v.w;
    float s2 = v.x*v.x + v.y*v.y + v.z*v.z + v.w*v.w;
    __shared__ float sm1[8], sm2[8];
    __shared__ float mu_s, inv_s;
    s = warp_sum(s); s2 = warp_sum(s2);
    if ((tid & 31) == 0) { sm1[tid >> 5] = s; sm2[tid >> 5] = s2; }
    __syncthreads();
    if (tid == 0) {
        float ts = 0.f, ts2 = 0.f;
        #pragma unroll
        for (int i = 0; i < 8; i++) { ts += sm1[i]; ts2 += sm2[i]; }
        float mu = ts / (float)D_;
        float var = ts2 / (float)D_ - mu * mu;
        mu_s = mu; inv_s = rsqrtf(var + 1e-5f);
    }
    __syncthreads();
    float mu = mu_s, inv = inv_s;
    float4 wv = ((const float4*)w)[tid];
    float4 bv = ((const float4*)bb)[tid];
    float4 o;
    o.x = (v.x - mu) * inv * wv.x + bv.x;
    o.y = (v.y - mu) * inv * wv.y + bv.y;
    o.z = (v.z - mu) * inv * wv.z + bv.z;
    o.w = (v.w - mu) * inv * wv.w + bv.w;
    ((float4*)(out + (size_t)row * D_))[tid] = o;
}

// ---------------- tf32 tensor-core GEMM NT ----------------------------------
// C = alpha*(A·B^T + bias) [+ resid].  A: MxK rm, B: NxK rm. 128x128x16,
// 8 warps (2x4), warp tile 64x32 via mma.sync m16n8k8 tf32, double-buffered.
__global__ void __launch_bounds__(256, 2) sgemm_tf32(
    const float* __restrict__ A, const float* __restrict__ Bm,
    const float* __restrict__ bias, const float* __restrict__ resid,
    float alpha, float* __restrict__ C, int M, int N, int K)
{
    __shared__ uint32_t As[2][16][128];
    __shared__ uint32_t Bs[2][16][128];
    int tid = threadIdx.x;
    int bm = blockIdx.y * 128, bn = blockIdx.x * 128;
    int r0 = tid >> 2;
    int kc = (tid & 3) * 4;
    const float* Ap = A + (size_t)(bm + r0) * K + kc;
    const float* Bp = Bm + (size_t)(bn + r0) * K + kc;

    int warp = tid >> 5, lane = tid & 31;
    int mw = (warp >> 2) * 64;
    int nw = (warp & 3) * 32;
    int gr = lane >> 2, c4 = lane & 3;

    float acc[4][4][4];
    #pragma unroll
    for (int i = 0; i < 4; i++)
        #pragma unroll
        for (int j = 0; j < 4; j++)
            #pragma unroll
            for (int l = 0; l < 4; l++) acc[i][j][l] = 0.f;

    float4 ra0, ra1, rb0, rb1;

    ra0 = *(const float4*)(Ap);
    ra1 = *(const float4*)(Ap + (size_t)64 * K);
    rb0 = *(const float4*)(Bp);
    rb1 = *(const float4*)(Bp + (size_t)64 * K);
    #pragma unroll
    for (int j = 0; j < 4; j++) {
        int k = kc + j, sw = SW(k);
        As[0][k][r0 ^ sw]        = f2tf32(((float*)&ra0)[j]);
        As[0][k][(r0 + 64) ^ sw] = f2tf32(((float*)&ra1)[j]);
        Bs[0][k][r0 ^ sw]        = f2tf32(((float*)&rb0)[j]);
        Bs[0][k][(r0 + 64) ^ sw] = f2tf32(((float*)&rb1)[j]);
    }
    __syncthreads();

    int nkt = K >> 4;
    int buf = 0;
    for (int kt = 0; kt < nkt; ++kt) {
        if (kt + 1 < nkt) {
            const float* Ap2 = Ap + (kt + 1) * 16;
            const float* Bp2 = Bp + (kt + 1) * 16;
            ra0 = *(const float4*)(Ap2);
            ra1 = *(const float4*)(Ap2 + (size_t)64 * K);
            rb0 = *(const float4*)(Bp2);
            rb1 = *(const float4*)(Bp2 + (size_t)64 * K);
        }
        #pragma unroll
        for (int ks = 0; ks < 16; ks += 8) {
            int k0 = ks + c4, k1 = ks + c4 + 4;
            int s0 = SW(k0), s1 = SW(k1);
            uint32_t af[4][4], bfr[4][2];
            #pragma unroll
            for (int mi = 0; mi < 4; mi++) {
                int m = mw + mi * 16 + gr;
                af[mi][0] = As[buf][k0][m ^ s0];
                af[mi][1] = As[buf][k0][(m + 8) ^ s0];
                af[mi][2] = As[buf][k1][m ^ s1];
                af[mi][3] = As[buf][k1][(m + 8) ^ s1];
            }
            #pragma unroll
            for (int ni = 0; ni < 4; ni++) {
                int n = nw + ni * 8 + gr;
                bfr[ni][0] = Bs[buf][k0][n ^ s0];
                bfr[ni][1] = Bs[buf][k1][n ^ s1];
            }
            #pragma unroll
            for (int mi = 0; mi < 4; mi++)
                #pragma unroll
                for (int ni = 0; ni < 4; ni++)
                    mma_tf32(acc[mi][ni], af[mi], bfr[ni]);
        }
        if (kt + 1 < nkt) {
            buf ^= 1;
            #pragma unroll
            for (int j = 0; j < 4; j++) {
                int k = kc + j, sw = SW(k);
                As[buf][k][r0 ^ sw]        = f2tf32(((float*)&ra0)[j]);
                As[buf][k][(r0 + 64) ^ sw] = f2tf32(((float*)&ra1)[j]);
                Bs[buf][k][r0 ^ sw]        = f2tf32(((float*)&rb0)[j]);
                Bs[buf][k][(r0 + 64) ^ sw] = f2tf32(((float*)&rb1)[j]);
            }
            __syncthreads();
        }
    }

    #pragma unroll
    for (int ni = 0; ni < 4; ni++) {
        int ng = bn + nw + ni * 8 + c4 * 2;
        float2 b2 = *(const float2*)&bias[ng];
        #pragma unroll
        for (int mi = 0; mi < 4; mi++) {
            int mg = bm + mw + mi * 16 + gr;
            float2 lo, hi;
            lo.x = (acc[mi][ni][0] + b2.x) * alpha;
            lo.y = (acc[mi][ni][1] + b2.y) * alpha;
            hi.x = (acc[mi][ni][2] + b2.x) * alpha;
            hi.y = (acc[mi][ni][3] + b2.y) * alpha;
            if (resid) {
                float2 r1 = *(const float2*)&resid[(size_t)mg * N + ng];
                float2 r2 = *(const float2*)&resid[(size_t)(mg + 8) * N + ng];
                lo.x += r1.x; lo.y += r1.y;
                hi.x += r2.x; hi.y += r2.y;
            }
            *(float2*)&C[(size_t)mg * N + ng]       = lo;
            *(float2*)&C[(size_t)(mg + 8) * N + ng] = hi;
        }
    }
}

// ---------------- grep gate: one warp per (b,h,t) ---------------------------
__global__ void gate_kernel(const float* __restrict__ q, const float* __restrict__ gw,
                            const float* __restrict__ gb, const float* __restrict__ ga,
                            float* __restrict__ gate)
{
    __shared__ float sgw[8][64];
    int tid = threadIdx.x;
    ((float*)sgw)[tid]       = gw[tid];
    ((float*)sgw)[tid + 256] = gw[tid + 256];
    __syncthreads();
    int warp = tid >> 5, lane = tid & 31;
    size_t z = (size_t)blockIdx.x * 8 + warp;
    int t = (int)(z % T_);
    int h = (int)((z / T_) % H_);
    int b = (int)(z / ((size_t)H_ * T_));
    const float* qr = q + ((size_t)b * T_ + t) * D_ + h * HD_;
    float q0 = qr[lane] * 256.f;
    float q1 = qr[lane + 32] * 256.f;
    float y[8];
    #pragma unroll
    for (int j = 0; j < 8; j++)
        y[j] = q0 * sgw[j][lane] + q1 * sgw[j][lane + 32];
    #pragma unroll
    for (int o = 16; o > 0; o >>= 1)
        #pragma unroll
        for (int j = 0; j < 8; j++) y[j] += __shfl_xor_sync(0xffffffffu, y[j], o);
    if (lane == 0) {
        float s0 = y[0]+y[1]+y[2]+y[3] + gb[0]+gb[1]+gb[2]+gb[3];
        float s1 = y[4]+y[5]+y[6]+y[7] + gb[4]+gb[5]+gb[6]+gb[7];
        float ga_ = 1.f / (1.f + expf(-s0));
        float gbv = 1.f / (1.f + expf(-s1));
        gate[z] = ga_ * (gbv * ga[h] - 1.f) + 2.f;
    }
}

// ---------------- relative-position bias table: pb[h][rel+1023] -------------
__global__ void pbtable_kernel(const float* __restrict__ rel_emb, float* __restrict__ pb)
{
    int i = blockIdx.x * 256 + threadIdx.x;
    if (i >= 2048) return;
    if (i == 2047) {
        for (int h = 0; h < H_; h++) pb[h * 2048 + i] = 0.f;
        return;
    }
    int rel = i - 1023;
    int bucket = (rel > 0) ? 160 : 0;
    int n = abs(rel);
    int idx;
    if (n < 80) {
        idx = bucket + n;
    } else {
        double nf = (double)n;
        int large = 80 + (int)(log(nf / 80.0) / log(10.0) * 80.0);
        if (large > 159) large = 159;
        idx = bucket + large;
    }
    for (int h = 0; h < H_; h++) pb[h * 2048 + i] = rel_emb[idx * H_ + h];
}

// ---------------- pos_bias_out writer: (B*H, T, T) broadcast ----------------
__global__ void posbias_kernel(const float* __restrict__ pb, float* __restrict__ out)
{
    size_t gid = (size_t)blockIdx.x * 256 + threadIdx.x;
    int s4 = (int)(gid & 255);
    int t  = (int)((gid >> 8) & 1023);
    int bh = (int)(gid >> 18);
    int h  = bh & 15;
    const float* row = pb + h * 2048 + 1023 - t;
    int s = s4 * 4;
    float4 o = make_float4(row[s], row[s+1], row[s+2], row[s+3]);
    ((float4*)out)[gid] = o;
}

// ---------------- tf32 QK^T + gate*pb epilogue -------------------------------
// grid (T/128, T/128, BH); K=64, row stride D_. Same mma layout as sgemm_tf32.
__global__ void __launch_bounds__(256, 2) qk_scores_tf32(
    const float* __restrict__ q, const float* __restrict__ k,
    const float* __restrict__ gate, const float* __restrict__ pb,
    float* __restrict__ scores)
{
    int z = blockIdx.z;
    int b = z / H_, h = z % H_;
    const float* A  = q + (size_t)b * T_ * D_ + h * HD_;
    const float* Bm = k + (size_t)b * T_ * D_ + h * HD_;
    float* C = scores + (size_t)z * T_ * T_;

    __shared__ uint32_t As[2][16][128];
    __shared__ uint32_t Bs[2][16][128];
    __shared__ float pbs[256];
    __shared__ float gs[128];

    int tid = threadIdx.x;
    int bm = blockIdx.y * 128, bn = blockIdx.x * 128;
    int base = bn - bm + 896;
    pbs[tid] = pb[h * 2048 + base + tid];
    if (tid < 128) gs[tid] = gate[(size_t)z * T_ + bm + tid];

    int r0 = tid >> 2;
    int kc = (tid & 3) * 4;
    const float* Ap = A + (size_t)(bm + r0) * D_ + kc;
    const float* Bp = Bm + (size_t)(bn + r0) * D_ + kc;

    int warp = tid >> 5, lane = tid & 31;
    int mw = (warp >> 2) * 64;
    int nw = (warp & 3) * 32;
    int gr = lane >> 2, c4 = lane & 31 & 3;

    float acc[4][4][4];
    #pragma unroll
    for (int i = 0; i < 4; i++)
        #pragma unroll
        for (int j = 0; j < 4; j++)
            #pragma unroll
            for (int l = 0; l < 4; l++) acc[i][j][l] = 0.f;

    float4 ra0, ra1, rb0, rb1;

    ra0 = *(const float4*)(Ap);
    ra1 = *(const float4*)(Ap + (size_t)64 * D_);
    rb0 = *(const float4*)(Bp);
    rb1 = *(const float4*)(Bp + (size_t)64 * D_);
    #pragma unroll
    for (int j = 0; j < 4; j++) {
        int kk = kc + j, sw = SW(kk);
        As[0][kk][r0 ^ sw]        = f2tf32(((float*)&ra0)[j]);
        As[0][kk][(r0 + 64) ^ sw] = f2tf32(((float*)&ra1)[j]);
        Bs[0][kk][r0 ^ sw]        = f2tf32(((float*)&rb0)[j]);
        Bs[0][kk][(r0 + 64) ^ sw] = f2tf32(((float*)&rb1)[j]);
    }
    __syncthreads();

    int buf = 0;
    #pragma unroll
    for (int kt = 0; kt < 4; ++kt) {
        if (kt + 1 < 4) {
            const float* Ap2 = Ap + (kt + 1) * 16;
            const float* Bp2 = Bp + (kt + 1) * 16;
            ra0 = *(const float4*)(Ap2);
            ra1 = *(const float4*)(Ap2 + (size_t)64 * D_);
            rb0 = *(const float4*)(Bp2);
            rb1 = *(const float4*)(Bp2 + (size_t)64 * D_);
        }
        #pragma unroll
        for (int ks = 0; ks < 16; ks += 8) {
            int k0 = ks + c4, k1 = ks + c4 + 4;
            int s0 = SW(k0), s1 = SW(k1);
            uint32_t af[4][4], bfr[4][2];
            #pragma unroll
            for (int mi = 0; mi < 4; mi++) {
                int m = mw + mi * 16 + gr;
                af[mi][0] = As[buf][k0][m ^ s0];
                af[mi][1] = As[buf][k0][(m + 8) ^ s0];
                af[mi][2] = As[buf][k1][m ^ s1];
                af[mi][3] = As[buf][k1][(m + 8) ^ s1];
            }
            #pragma unroll
            for (int ni = 0; ni < 4; ni++) {
                int n = nw + ni * 8 + gr;
                bfr[ni][0] = Bs[buf][k0][n ^ s0];
                bfr[ni][1] = Bs[buf][k1][n ^ s1];
            }
            #pragma unroll
            for (int mi = 0; mi < 4; mi++)
                #pragma unroll
                for (int ni = 0; ni < 4; ni++)
                    mma_tf32(acc[mi][ni], af[mi], bfr[ni]);
        }
        if (kt + 1 < 4) {
            buf ^= 1;
            #pragma unroll
            for (int j = 0; j < 4; j++) {
                int kk = kc + j, sw = SW(kk);
                As[buf][kk][r0 ^ sw]        = f2tf32(((float*)&ra0)[j]);
                As[buf][kk][(r0 + 64) ^ sw] = f2tf32(((float*)&ra1)[j]);
                Bs[buf][kk][r0 ^ sw]        = f2tf32(((float*)&rb0)[j]);
                Bs[buf][kk][(r0 + 64) ^ sw] = f2tf32(((float*)&rb1)[j]);
            }
            __syncthreads();
        }
    }

    // epilogue: + gate[row]*pb[col-row]
    #pragma unroll
    for (int ni = 0; ni < 4; ni++) {
        int nloc = nw + ni * 8 + c4 * 2;
        #pragma unroll
        for (int mi = 0; mi < 4; mi++) {
            int m0 = mw + mi * 16 + gr;
            int m1 = m0 + 8;
            float g0 = gs[m0], g1 = gs[m1];
            float2 lo, hi;
            lo.x = acc[mi][ni][0] + g0 * pbs[nloc     - m0 + 127];
            lo.y = acc[mi][ni][1] + g0 * pbs[nloc + 1 - m0 + 127];
            hi.x = acc[mi][ni][2] + g1 * pbs[nloc     - m1 + 127];
            hi.y = acc[mi][ni][3] + g1 * pbs[nloc + 1 - m1 + 127];
            *(float2*)&C[(size_t)(bm + m0) * T_ + bn + nloc] = lo;
            *(float2*)&C[(size_t)(bm + m1) * T_ + bn + nloc] = hi;
        }
    }
}

// ---------------- softmax row stats: {max, 1/sum(exp)} ----------------------
__global__ void softmax_stats(const float* __restrict__ s, float2* __restrict__ stats)
{
    size_t row = blockIdx.x;
    const float4* p = (const float4*)(s + row * (size_t)T_);
    int tid = threadIdx.x;
    float4 v = p[tid];
    __shared__ float sm[8];
    __shared__ float bmax, bsum;
    float m = fmaxf(fmaxf(v.x, v.y), fmaxf(v.z, v.w));
    m = warp_max(m);
    if ((tid & 31) == 0) sm[tid >> 5] = m;
    __syncthreads();
    if (tid == 0) {
        float t = sm[0];
        #pragma unroll
        for (int i = 1; i < 8; i++) t = fmaxf(t, sm[i]);
        bmax = t;
    }
    __syncthreads();
    m = bmax;
    float su = __expf(v.x - m) + __expf(v.y - m) + __expf(v.z - m) + __expf(v.w - m);
    su = warp_sum(su);
    __syncthreads();
    if ((tid & 31) == 0) sm[tid >> 5] = su;
    __syncthreads();
    if (tid == 0) {
        float t = 0.f;
        #pragma unroll
        for (int i = 0; i < 8; i++) t += sm[i];
        bsum = t;
    }
    __syncthreads();
    if (tid == 0) stats[row] = make_float2(m, 1.f / bsum);
}

// ---------------- tf32 attn·V with fused softmax normalization --------------
// ctx[t,d] = sum_s exp(sc[t,s]-m)*inv * v[s,d].  BM=128, BN=64, BK=16 x64, db.
// 8 warps as 4x2; warp tile 32x32 (mi:2 x16, ni:4 x8).
__global__ void __launch_bounds__(256, 2) av_gemm_tf32(
    const float* __restrict__ sc, const float2* __restrict__ stats,
    const float* __restrict__ v, float* __restrict__ ctx)
{
    int z = blockIdx.z;
    int b = z / H_, h = z % H_;
    const float* A  = sc + (size_t)z * T_ * T_;              // lda = T
    const float* Bm = v + (size_t)b * T_ * D_ + h * HD_;     // ldb = D
    float* C = ctx + (size_t)b * T_ * D_ + h * HD_;          // ldc = D

    __shared__ uint32_t As[2][16][128];
    __shared__ uint32_t Bs[2][16][64];

    int tid = threadIdx.x;
    int bm = blockIdx.y * 128;
    int r0 = tid >> 2;              // 0..63 A rows
    int kc = (tid & 3) * 4;         // A k-chunk
    int bkr = tid >> 4;             // 0..15 B k-row
    int bcol = (tid & 15) * 4;      // B col

    int warp = tid >> 5, lane = tid & 31;
    int mw = (warp >> 1) * 32;      // 4 warp rows x 32
    int nw = (warp & 1) * 32;       // 2 warp cols x 32
    int gr = lane >> 2, c4 = lane & 3;

    float2 st0 = stats[(size_t)z * T_ + bm + r0];
    float2 st1 = stats[(size_t)z * T_ + bm + r0 + 64];

    const float* Ap = A + (size_t)(bm + r0) * T_ + kc;

    float acc[2][4][4];
    #pragma unroll
    for (int i = 0; i < 2; i++)
        #pragma unroll
        for (int j = 0; j < 4; j++)
            #pragma unroll
            for (int l = 0; l < 4; l++) acc[i][j][l] = 0.f;

    float4 ra0, ra1, rb;

    // prologue
    ra0 = *(const float4*)(Ap);
    ra1 = *(const float4*)(Ap + (size_t)64 * T_);
    rb  = *(const float4*)(Bm + (size_t)bkr * D_ + bcol);
    {
        int swb = SWB(bkr);
        #pragma unroll
        for (int j = 0; j < 4; j++) {
            int kk = kc + j, sw = SW(kk);
            As[0][kk][r0 ^ sw]        = f2tf32(__expf(((float*)&ra0)[j] - st0.x) * st0.y);
            As[0][kk][(r0 + 64) ^ sw] = f2tf32(__expf(((float*)&ra1)[j] - st1.x) * st1.y);
            Bs[0][bkr][(bcol ^ swb) + j] = f2tf32(((float*)&rb)[j]);
        }
    }
    __syncthreads();

    int buf = 0;
    for (int kt = 0; kt < 64; ++kt) {
        if (kt + 1 < 64) {
            ra0 = *(const float4*)(Ap + (kt + 1) * 16);
            ra1 = *(const float4*)(Ap + (kt + 1) * 16 + (size_t)64 * T_);
            rb  = *(const float4*)(Bm + (size_t)((kt + 1) * 16 + bkr) * D_ + bcol);
        }
        #pragma unroll
        for (int ks = 0; ks < 16; ks += 8) {
            int k0 = ks + c4, k1 = ks + c4 + 4;
            int s0 = SW(k0), s1 = SW(k1);
            int sb = SWB(c4);       // (k&3)<<3 same for k0,k1
            uint32_t af[2][4], bfr[4][2];
            #pragma unroll
            for (int mi = 0; mi < 2; mi++) {
                int m = mw + mi * 16 + gr;
                af[mi][0] = As[buf][k0][m ^ s0];
                af[mi][1] = As[buf][k0][(m + 8) ^ s0];
                af[mi][2] = As[buf][k1][m ^ s1];
                af[mi][3] = As[buf][k1][(m + 8) ^ s1];
            }
            #pragma unroll
            for (int ni = 0; ni < 4; ni++) {
                int n = nw + ni * 8 + gr;
                bfr[ni][0] = Bs[buf][k0][n ^ sb];
                bfr[ni][1] = Bs[buf][k1][n ^ sb];
            }
            #pragma unroll
            for (int mi = 0; mi < 2; mi++)
                #pragma unroll
                for (int ni = 0; ni < 4; ni++)
                    mma_tf32(acc[mi][ni], af[mi], bfr[ni]);
        }
        if (kt + 1 < 64) {
            buf ^= 1;
            int swb = SWB(bkr);
            #pragma unroll
            for (int j = 0; j < 4; j++) {
                int kk = kc + j, sw = SW(kk);
                As[buf][kk][r0 ^ sw]        = f2tf32(__expf(((float*)&ra0)[j] - st0.x) * st0.y);
                As[buf][kk][(r0 + 64) ^ sw] = f2tf32(__expf(((float*)&ra1)[j] - st1.x) * st1.y);
                Bs[buf][bkr][(bcol ^ swb) + j] = f2tf32(((float*)&rb)[j]);
            }
            __syncthreads();
        }
    }

    #pragma unroll
    for (int ni = 0; ni < 4; ni++) {
        int ng = nw + ni * 8 + c4 * 2;
        #pragma unroll
        for (int mi = 0; mi < 2; mi++) {
            int mg = bm + mw + mi * 16 + gr;
            *(float2*)&C[(size_t)mg * D_ + ng]       = make_float2(acc[mi][ni][0], acc[mi][ni][1]);
            *(float2*)&C[(size_t)(mg + 8) * D_ + ng] = make_float2(acc[mi][ni][2], acc[mi][ni][3]);
        }
    }
}

// ---------------- host launcher ---------------------------------------------
extern "C" void kernel_launch(void* const* d_in, const int* in_sizes, int n_in,
                              void* d_out, int out_size)
{
    const float* x      = (const float*)d_in[0];
    const float* ln_w   = (const float*)d_in[1];
    const float* ln_b   = (const float*)d_in[2];
    const float* wq     = (const float*)d_in[3];
    const float* bq     = (const float*)d_in[4];
    const float* wk     = (const float*)d_in[5];
    const float* bk     = (const float*)d_in[6];
    const float* wv     = (const float*)d_in[7];
    const float* bv     = (const float*)d_in[8];
    const float* wo     = (const float*)d_in[9];
    const float* bo     = (const float*)d_in[10];
    const float* rel_e  = (const float*)d_in[11];
    const float* grep_w = (const float*)d_in[12];
    const float* grep_b = (const float*)d_in[13];
    const float* grep_a = (const float*)d_in[14];

    float* out     = (float*)d_out;
    float* pos_out = out + (size_t)B_ * T_ * D_;

    float *p_h, *p_q, *p_k, *p_v, *p_ctx, *p_gate, *p_pb, *p_sc;
    float2* p_st;
    cudaGetSymbolAddress((void**)&p_h,    g_h);
    cudaGetSymbolAddress((void**)&p_q,    g_q);
    cudaGetSymbolAddress((void**)&p_k,    g_k);
    cudaGetSymbolAddress((void**)&p_v,    g_v);
    cudaGetSymbolAddress((void**)&p_ctx,  g_ctx);
    cudaGetSymbolAddress((void**)&p_gate, g_gate);
    cudaGetSymbolAddress((void**)&p_pb,   g_pb);
    cudaGetSymbolAddress((void**)&p_st,   g_stats);
    cudaGetSymbolAddress((void**)&p_sc,   g_scores);

    // 1. LayerNorm
    ln_kernel<<<B_*T_, 256>>>(x, ln_w, ln_b, p_h);

    // 2. QKV projections (tf32 tensor-core NT GEMMs); q carries 64^-0.5
    dim3 g1(D_/128, (B_*T_)/128);
    sgemm_tf32<<<g1, 256>>>(p_h, wq, bq, nullptr, 0.125f, p_q, B_*T_, D_, D_);
    sgemm_tf32<<<g1, 256>>>(p_h, wk, bk, nullptr, 1.0f,   p_k, B_*T_, D_, D_);
    sgemm_tf32<<<g1, 256>>>(p_h, wv, bv, nullptr, 1.0f,   p_v, B_*T_, D_, D_);

    // 3. grep gate
    gate_kernel<<<(BH_*T_)/8, 256>>>(p_q, grep_w, grep_b, grep_a, p_gate);

    // 4. rel-position bias table + broadcast output
    pbtable_kernel<<<8, 256>>>(rel_e, p_pb);
    posbias_kernel<<<65536, 256>>>(p_pb, pos_out);

    // 5. scores = q k^T + gate * pos_bias (tf32 mma)
    qk_scores_tf32<<<dim3(T_/128, T_/128, BH_), 256>>>(p_q, p_k, p_gate, p_pb, p_sc);

    // 6. softmax row stats only (normalization fused into av_gemm)
    softmax_stats<<<BH_*T_, 256>>>(p_sc, p_st);

    // 7. ctx = softmax(scores) @ v (tf32 mma, written in (B,T,D) layout)
    av_gemm_tf32<<<dim3(1, T_/128, BH_), 256>>>(p_sc, p_st, p_v, p_ctx);

    // 8. out = ctx @ wo^T + bo + x
    sgemm_tf32<<<g1, 256>>>(p_ctx, wo, bo, x, 1.0f, out, B_*T_, D_, D_);
}

// round 8
// speedup vs baseline: 2.1946x; 1.4193x over previous
#include <cuda_runtime.h>
#include <cuda_fp16.h>
#include <math.h>
#include <stdint.h>

#define B_ 4
#define T_ 1024
#define D_ 1024
#define H_ 16
#define HD_ 64
#define BH_ 64

// XOR swizzle for tf32 smem tiles (width-128 rows)
#define SW(k) ((((k) ^ ((k) >> 2)) & 3) << 3)

// ---------------- scratch (__device__ globals; no allocations allowed) -----
__device__ float g_h[B_*T_*D_];
__device__ float g_q[B_*T_*D_];
__device__ float g_k[B_*T_*D_];
__device__ float g_v[B_*T_*D_];
__device__ float g_ctx[B_*T_*D_];
__device__ float g_gate[BH_*T_];
__device__ float g_pb[H_*2048];

// ---------------- helpers ---------------------------------------------------
__device__ __forceinline__ float warp_sum(float v) {
    #pragma unroll
    for (int o = 16; o > 0; o >>= 1) v += __shfl_xor_sync(0xffffffffu, v, o);
    return v;
}
__device__ __forceinline__ uint32_t f2tf32(float f) {
    uint32_t u;
    asm("cvt.rna.tf32.f32 %0, %1;" : "=r"(u) : "f"(f));
    return u;
}
__device__ __forceinline__ void mma_tf32(float* c, const uint32_t* a, const uint32_t* b) {
    asm volatile(
        "mma.sync.aligned.m16n8k8.row.col.f32.tf32.tf32.f32 "
        "{%0,%1,%2,%3}, {%4,%5,%6,%7}, {%8,%9}, {%0,%1,%2,%3};\n"
        : "+f"(c[0]), "+f"(c[1]), "+f"(c[2]), "+f"(c[3])
        : "r"(a[0]), "r"(a[1]), "r"(a[2]), "r"(a[3]), "r"(b[0]), "r"(b[1]));
}
__device__ __forceinline__ void mma_fp16(float* c, const uint32_t* a, const uint32_t* b) {
    asm volatile(
        "mma.sync.aligned.m16n8k16.row.col.f32.f16.f16.f32 "
        "{%0,%1,%2,%3}, {%4,%5,%6,%7}, {%8,%9}, {%0,%1,%2,%3};\n"
        : "+f"(c[0]), "+f"(c[1]), "+f"(c[2]), "+f"(c[3])
        : "r"(a[0]), "r"(a[1]), "r"(a[2]), "r"(a[3]), "r"(b[0]), "r"(b[1]));
}
__device__ __forceinline__ uint32_t pkh2(float a, float b) {
    __half2 h = __floats2half2_rn(a, b);
    return *(uint32_t*)&h;
}

// ---------------- LayerNorm: one block per row ------------------------------
__global__ void ln_kernel(const float* __restrict__ x, const float* __restrict__ w,
                          const float* __restrict__ bb, float* __restrict__ out)
{
    int row = blockIdx.x, tid = threadIdx.x;
    const float4* xr = (const float4*)(x + (size_t)row * D_);
    float4 v = xr[tid];
    float s  = v.x + v.y + v.z + v.w;
    float s2 = v.x*v.x + v.y*v.y + v.z*v.z + v.w*v.w;
    __shared__ float sm1[8], sm2[8];
    __shared__ float mu_s, inv_s;
    s = warp_sum(s); s2 = warp_sum(s2);
    if ((tid & 31) == 0) { sm1[tid >> 5] = s; sm2[tid >> 5] = s2; }
    __syncthreads();
    if (tid == 0) {
        float ts = 0.f, ts2 = 0.f;
        #pragma unroll
        for (int i = 0; i < 8; i++) { ts += sm1[i]; ts2 += sm2[i]; }
        float mu = ts / (float)D_;
        float var = ts2 / (float)D_ - mu * mu;
        mu_s = mu; inv_s = rsqrtf(var + 1e-5f);
    }
    __syncthreads();
    float mu = mu_s, inv = inv_s;
    float4 wv = ((const float4*)w)[tid];
    float4 bv = ((const float4*)bb)[tid];
    float4 o;
    o.x = (v.x - mu) * inv * wv.x + bv.x;
    o.y = (v.y - mu) * inv * wv.y + bv.y;
    o.z = (v.z - mu) * inv * wv.z + bv.z;
    o.w = (v.w - mu) * inv * wv.w + bv.w;
    ((float4*)(out + (size_t)row * D_))[tid] = o;
}

// ---------------- tf32 tensor-core GEMM NT ----------------------------------
__global__ void __launch_bounds__(256, 2) sgemm_tf32(
    const float* __restrict__ A, const float* __restrict__ Bm,
    const float* __restrict__ bias, const float* __restrict__ resid,
    float alpha, float* __restrict__ C, int M, int N, int K)
{
    __shared__ uint32_t As[2][16][128];
    __shared__ uint32_t Bs[2][16][128];
    int tid = threadIdx.x;
    int bm = blockIdx.y * 128, bn = blockIdx.x * 128;
    int r0 = tid >> 2;
    int kc = (tid & 3) * 4;
    const float* Ap = A + (size_t)(bm + r0) * K + kc;
    const float* Bp = Bm + (size_t)(bn + r0) * K + kc;

    int warp = tid >> 5, lane = tid & 31;
    int mw = (warp >> 2) * 64;
    int nw = (warp & 3) * 32;
    int gr = lane >> 2, c4 = lane & 3;

    float acc[4][4][4];
    #pragma unroll
    for (int i = 0; i < 4; i++)
        #pragma unroll
        for (int j = 0; j < 4; j++)
            #pragma unroll
            for (int l = 0; l < 4; l++) acc[i][j][l] = 0.f;

    float4 ra0, ra1, rb0, rb1;

    ra0 = *(const float4*)(Ap);
    ra1 = *(const float4*)(Ap + (size_t)64 * K);
    rb0 = *(const float4*)(Bp);
    rb1 = *(const float4*)(Bp + (size_t)64 * K);
    #pragma unroll
    for (int j = 0; j < 4; j++) {
        int k = kc + j, sw = SW(k);
        As[0][k][r0 ^ sw]        = f2tf32(((float*)&ra0)[j]);
        As[0][k][(r0 + 64) ^ sw] = f2tf32(((float*)&ra1)[j]);
        Bs[0][k][r0 ^ sw]        = f2tf32(((float*)&rb0)[j]);
        Bs[0][k][(r0 + 64) ^ sw] = f2tf32(((float*)&rb1)[j]);
    }
    __syncthreads();

    int nkt = K >> 4;
    int buf = 0;
    for (int kt = 0; kt < nkt; ++kt) {
        if (kt + 1 < nkt) {
            const float* Ap2 = Ap + (kt + 1) * 16;
            const float* Bp2 = Bp + (kt + 1) * 16;
            ra0 = *(const float4*)(Ap2);
            ra1 = *(const float4*)(Ap2 + (size_t)64 * K);
            rb0 = *(const float4*)(Bp2);
            rb1 = *(const float4*)(Bp2 + (size_t)64 * K);
        }
        #pragma unroll
        for (int ks = 0; ks < 16; ks += 8) {
            int k0 = ks + c4, k1 = ks + c4 + 4;
            int s0 = SW(k0), s1 = SW(k1);
            uint32_t af[4][4], bfr[4][2];
            #pragma unroll
            for (int mi = 0; mi < 4; mi++) {
                int m = mw + mi * 16 + gr;
                af[mi][0] = As[buf][k0][m ^ s0];
                af[mi][1] = As[buf][k0][(m + 8) ^ s0];
                af[mi][2] = As[buf][k1][m ^ s1];
                af[mi][3] = As[buf][k1][(m + 8) ^ s1];
            }
            #pragma unroll
            for (int ni = 0; ni < 4; ni++) {
                int n = nw + ni * 8 + gr;
                bfr[ni][0] = Bs[buf][k0][n ^ s0];
                bfr[ni][1] = Bs[buf][k1][n ^ s1];
            }
            #pragma unroll
            for (int mi = 0; mi < 4; mi++)
                #pragma unroll
                for (int ni = 0; ni < 4; ni++)
                    mma_tf32(acc[mi][ni], af[mi], bfr[ni]);
        }
        if (kt + 1 < nkt) {
            buf ^= 1;
            #pragma unroll
            for (int j = 0; j < 4; j++) {
                int k = kc + j, sw = SW(k);
                As[buf][k][r0 ^ sw]        = f2tf32(((float*)&ra0)[j]);
                As[buf][k][(r0 + 64) ^ sw] = f2tf32(((float*)&ra1)[j]);
                Bs[buf][k][r0 ^ sw]        = f2tf32(((float*)&rb0)[j]);
                Bs[buf][k][(r0 + 64) ^ sw] = f2tf32(((float*)&rb1)[j]);
            }
            __syncthreads();
        }
    }

    #pragma unroll
    for (int ni = 0; ni < 4; ni++) {
        int ng = bn + nw + ni * 8 + c4 * 2;
        float2 b2 = *(const float2*)&bias[ng];
        #pragma unroll
        for (int mi = 0; mi < 4; mi++) {
            int mg = bm + mw + mi * 16 + gr;
            float2 lo, hi;
            lo.x = (acc[mi][ni][0] + b2.x) * alpha;
            lo.y = (acc[mi][ni][1] + b2.y) * alpha;
            hi.x = (acc[mi][ni][2] + b2.x) * alpha;
            hi.y = (acc[mi][ni][3] + b2.y) * alpha;
            if (resid) {
                float2 r1 = *(const float2*)&resid[(size_t)mg * N + ng];
                float2 r2 = *(const float2*)&resid[(size_t)(mg + 8) * N + ng];
                lo.x += r1.x; lo.y += r1.y;
                hi.x += r2.x; hi.y += r2.y;
            }
            *(float2*)&C[(size_t)mg * N + ng]       = lo;
            *(float2*)&C[(size_t)(mg + 8) * N + ng] = hi;
        }
    }
}

// ---------------- grep gate: one warp per (b,h,t) ---------------------------
__global__ void gate_kernel(const float* __restrict__ q, const float* __restrict__ gw,
                            const float* __restrict__ gb, const float* __restrict__ ga,
                            float* __restrict__ gate)
{
    __shared__ float sgw[8][64];
    int tid = threadIdx.x;
    ((float*)sgw)[tid]       = gw[tid];
    ((float*)sgw)[tid + 256] = gw[tid + 256];
    __syncthreads();
    int warp = tid >> 5, lane = tid & 31;
    size_t z = (size_t)blockIdx.x * 8 + warp;
    int t = (int)(z % T_);
    int h = (int)((z / T_) % H_);
    int b = (int)(z / ((size_t)H_ * T_));
    const float* qr = q + ((size_t)b * T_ + t) * D_ + h * HD_;
    float q0 = qr[lane] * 256.f;
    float q1 = qr[lane + 32] * 256.f;
    float y[8];
    #pragma unroll
    for (int j = 0; j < 8; j++)
        y[j] = q0 * sgw[j][lane] + q1 * sgw[j][lane + 32];
    #pragma unroll
    for (int o = 16; o > 0; o >>= 1)
        #pragma unroll
        for (int j = 0; j < 8; j++) y[j] += __shfl_xor_sync(0xffffffffu, y[j], o);
    if (lane == 0) {
        float s0 = y[0]+y[1]+y[2]+y[3] + gb[0]+gb[1]+gb[2]+gb[3];
        float s1 = y[4]+y[5]+y[6]+y[7] + gb[4]+gb[5]+gb[6]+gb[7];
        float ga_ = 1.f / (1.f + expf(-s0));
        float gbv = 1.f / (1.f + expf(-s1));
        gate[z] = ga_ * (gbv * ga[h] - 1.f) + 2.f;
    }
}

// ---------------- relative-position bias table: pb[h][rel+1023] -------------
__global__ void pbtable_kernel(const float* __restrict__ rel_emb, float* __restrict__ pb)
{
    int i = blockIdx.x * 256 + threadIdx.x;
    if (i >= 2048) return;
    if (i == 2047) {
        for (int h = 0; h < H_; h++) pb[h * 2048 + i] = 0.f;
        return;
    }
    int rel = i - 1023;
    int bucket = (rel > 0) ? 160 : 0;
    int n = abs(rel);
    int idx;
    if (n < 80) {
        idx = bucket + n;
    } else {
        double nf = (double)n;
        int large = 80 + (int)(log(nf / 80.0) / log(10.0) * 80.0);
        if (large > 159) large = 159;
        idx = bucket + large;
    }
    for (int h = 0; h < H_; h++) pb[h * 2048 + i] = rel_emb[idx * H_ + h];
}

// ---------------- pos_bias_out writer: (B*H, T, T) broadcast ----------------
__global__ void posbias_kernel(const float* __restrict__ pb, float* __restrict__ out)
{
    size_t gid = (size_t)blockIdx.x * 256 + threadIdx.x;
    int s4 = (int)(gid & 255);
    int t  = (int)((gid >> 8) & 1023);
    int bh = (int)(gid >> 18);
    int h  = bh & 15;
    const float* row = pb + h * 2048 + 1023 - t;
    int s = s4 * 4;
    float4 o = make_float4(row[s], row[s+1], row[s+2], row[s+3]);
    ((float4*)out)[gid] = o;
}

// ---------------- flash attention: QK^T + bias + online softmax + PV --------
// grid (T/128, BH), 256 threads (8 warps). Warp w owns t-rows [w*16, w*16+16).
// fp16 mma m16n8k16; KV tiles of 64; scores never leave the SM.
__global__ void __launch_bounds__(256) flash_attn(
    const float* __restrict__ q, const float* __restrict__ k,
    const float* __restrict__ v, const float* __restrict__ gate,
    const float* __restrict__ pb, float* __restrict__ ctx)
{
    int z = blockIdx.y;
    int b = z >> 4, h = z & 15;
    int bm = blockIdx.x * 128;
    const float* Qg = q + (size_t)b * T_ * D_ + h * HD_;
    const float* Kg = k + (size_t)b * T_ * D_ + h * HD_;
    const float* Vg = v + (size_t)b * T_ * D_ + h * HD_;
    float* Cg = ctx + (size_t)b * T_ * D_ + h * HD_;

    __shared__ __half ks[64][72];    // [key][dim]
    __shared__ __half vs[64][72];    // [dim][key]  (V^T)
    __shared__ __half ps[128][72];   // [t][s]
    __shared__ float gs[128];
    __shared__ float pbs[192];

    int tid = threadIdx.x;
    int w = tid >> 5, lane = tid & 31;
    int gr = lane >> 2, c4 = lane & 3;
    int trow = w * 16 + gr;

    if (tid < 128) gs[tid] = gate[(size_t)z * T_ + bm + tid];

    // Q fragments: A-frags for 4 k16 blocks, rows trow/trow+8
    uint32_t qa[4][4];
    {
        const float* Q0 = Qg + (size_t)(bm + trow) * D_;
        const float* Q1 = Qg + (size_t)(bm + trow + 8) * D_;
        #pragma unroll
        for (int kb = 0; kb < 4; kb++) {
            int d0 = kb * 16 + 2 * c4;
            float2 f;
            f = *(const float2*)(Q0 + d0);     qa[kb][0] = pkh2(f.x, f.y);
            f = *(const float2*)(Q1 + d0);     qa[kb][1] = pkh2(f.x, f.y);
            f = *(const float2*)(Q0 + d0 + 8); qa[kb][2] = pkh2(f.x, f.y);
            f = *(const float2*)(Q1 + d0 + 8); qa[kb][3] = pkh2(f.x, f.y);
        }
    }

    float oacc[8][4];
    #pragma unroll
    for (int i = 0; i < 8; i++)
        #pragma unroll
        for (int j = 0; j < 4; j++) oacc[i][j] = 0.f;
    float m0 = -1e30f, m1 = -1e30f, l0 = 0.f, l1 = 0.f;

    for (int kv = 0; kv < 16; kv++) {
        __syncthreads();    // previous PV reads done; gs ready (iter 0)
        // fill K and V^T tiles (fp32 -> fp16)
        {
            int key = tid >> 2, d0 = (tid & 3) * 16;
            const float* Kr = Kg + (size_t)(kv * 64 + key) * D_ + d0;
            const float* Vr = Vg + (size_t)(kv * 64 + key) * D_ + d0;
            #pragma unroll
            for (int j = 0; j < 16; j += 4) {
                float4 kf = *(const float4*)(Kr + j);
                ks[key][d0 + j]     = __float2half_rn(kf.x);
                ks[key][d0 + j + 1] = __float2half_rn(kf.y);
                ks[key][d0 + j + 2] = __float2half_rn(kf.z);
                ks[key][d0 + j + 3] = __float2half_rn(kf.w);
                float4 vf = *(const float4*)(Vr + j);
                vs[d0 + j][key]     = __float2half_rn(vf.x);
                vs[d0 + j + 1][key] = __float2half_rn(vf.y);
                vs[d0 + j + 2][key] = __float2half_rn(vf.z);
                vs[d0 + j + 3][key] = __float2half_rn(vf.w);
            }
        }
        if (tid < 192) pbs[tid] = pb[h * 2048 + kv * 64 - bm + 896 + tid];
        __syncthreads();

        // S = Q K^T  (128 x 64)
        float sacc[8][4];
        #pragma unroll
        for (int i = 0; i < 8; i++)
            #pragma unroll
            for (int j = 0; j < 4; j++) sacc[i][j] = 0.f;
        #pragma unroll
        for (int kb = 0; kb < 4; kb++) {
            #pragma unroll
            for (int nb = 0; nb < 8; nb++) {
                uint32_t bf[2];
                bf[0] = *(const uint32_t*)&ks[nb * 8 + gr][kb * 16 + 2 * c4];
                bf[1] = *(const uint32_t*)&ks[nb * 8 + gr][kb * 16 + 2 * c4 + 8];
                mma_fp16(sacc[nb], qa[kb], bf);
            }
        }
        // + gate[t] * pb[s - t]
        float g0 = gs[trow], g1 = gs[trow + 8];
        #pragma unroll
        for (int nb = 0; nb < 8; nb++) {
            int i0 = nb * 8 + 2 * c4 - trow + 127;
            sacc[nb][0] += g0 * pbs[i0];
            sacc[nb][1] += g0 * pbs[i0 + 1];
            sacc[nb][2] += g1 * pbs[i0 - 8];
            sacc[nb][3] += g1 * pbs[i0 - 7];
        }
        // online softmax (rows trow, trow+8)
        float mx0 = -1e30f, mx1 = -1e30f;
        #pragma unroll
        for (int nb = 0; nb < 8; nb++) {
            mx0 = fmaxf(mx0, fmaxf(sacc[nb][0], sacc[nb][1]));
            mx1 = fmaxf(mx1, fmaxf(sacc[nb][2], sacc[nb][3]));
        }
        mx0 = fmaxf(mx0, __shfl_xor_sync(0xffffffffu, mx0, 1));
        mx0 = fmaxf(mx0, __shfl_xor_sync(0xffffffffu, mx0, 2));
        mx1 = fmaxf(mx1, __shfl_xor_sync(0xffffffffu, mx1, 1));
        mx1 = fmaxf(mx1, __shfl_xor_sync(0xffffffffu, mx1, 2));
        float mn0 = fmaxf(m0, mx0), mn1 = fmaxf(m1, mx1);
        float c0 = __expf(m0 - mn0), c1 = __expf(m1 - mn1);
        float su0 = 0.f, su1 = 0.f;
        #pragma unroll
        for (int nb = 0; nb < 8; nb++) {
            float p0 = __expf(sacc[nb][0] - mn0);
            float p1 = __expf(sacc[nb][1] - mn0);
            float p2 = __expf(sacc[nb][2] - mn1);
            float p3 = __expf(sacc[nb][3] - mn1);
            su0 += p0 + p1; su1 += p2 + p3;
            *(uint32_t*)&ps[trow][nb * 8 + 2 * c4]     = pkh2(p0, p1);
            *(uint32_t*)&ps[trow + 8][nb * 8 + 2 * c4] = pkh2(p2, p3);
        }
        su0 += __shfl_xor_sync(0xffffffffu, su0, 1);
        su0 += __shfl_xor_sync(0xffffffffu, su0, 2);
        su1 += __shfl_xor_sync(0xffffffffu, su1, 1);
        su1 += __shfl_xor_sync(0xffffffffu, su1, 2);
        l0 = l0 * c0 + su0; l1 = l1 * c1 + su1;
        m0 = mn0; m1 = mn1;
        #pragma unroll
        for (int nb = 0; nb < 8; nb++) {
            oacc[nb][0] *= c0; oacc[nb][1] *= c0;
            oacc[nb][2] *= c1; oacc[nb][3] *= c1;
        }
        __syncwarp();   // ps rows of this warp written by this warp only

        // O += P V  (128 x 64, k = 64)
        #pragma unroll
        for (int sb = 0; sb < 4; sb++) {
            uint32_t pa[4];
            pa[0] = *(const uint32_t*)&ps[trow][sb * 16 + 2 * c4];
            pa[1] = *(const uint32_t*)&ps[trow + 8][sb * 16 + 2 * c4];
            pa[2] = *(const uint32_t*)&ps[trow][sb * 16 + 2 * c4 + 8];
            pa[3] = *(const uint32_t*)&ps[trow + 8][sb * 16 + 2 * c4 + 8];
            #pragma unroll
            for (int nb = 0; nb < 8; nb++) {
                uint32_t bf[2];
                bf[0] = *(const uint32_t*)&vs[nb * 8 + gr][sb * 16 + 2 * c4];
                bf[1] = *(const uint32_t*)&vs[nb * 8 + gr][sb * 16 + 2 * c4 + 8];
                mma_fp16(oacc[nb], pa, bf);
            }
        }
    }

    // epilogue: O / l  ->  ctx
    float inv0 = 1.f / l0, inv1 = 1.f / l1;
    #pragma unroll
    for (int nb = 0; nb < 8; nb++) {
        int d = nb * 8 + 2 * c4;
        *(float2*)&Cg[(size_t)(bm + trow) * D_ + d] =
            make_float2(oacc[nb][0] * inv0, oacc[nb][1] * inv0);
        *(float2*)&Cg[(size_t)(bm + trow + 8) * D_ + d] =
            make_float2(oacc[nb][2] * inv1, oacc[nb][3] * inv1);
    }
}

// ---------------- host launcher ---------------------------------------------
extern "C" void kernel_launch(void* const* d_in, const int* in_sizes, int n_in,
                              void* d_out, int out_size)
{
    const float* x      = (const float*)d_in[0];
    const float* ln_w   = (const float*)d_in[1];
    const float* ln_b   = (const float*)d_in[2];
    const float* wq     = (const float*)d_in[3];
    const float* bq     = (const float*)d_in[4];
    const float* wk     = (const float*)d_in[5];
    const float* bk     = (const float*)d_in[6];
    const float* wv     = (const float*)d_in[7];
    const float* bv     = (const float*)d_in[8];
    const float* wo     = (const float*)d_in[9];
    const float* bo     = (const float*)d_in[10];
    const float* rel_e  = (const float*)d_in[11];
    const float* grep_w = (const float*)d_in[12];
    const float* grep_b = (const float*)d_in[13];
    const float* grep_a = (const float*)d_in[14];

    float* out     = (float*)d_out;
    float* pos_out = out + (size_t)B_ * T_ * D_;

    float *p_h, *p_q, *p_k, *p_v, *p_ctx, *p_gate, *p_pb;
    cudaGetSymbolAddress((void**)&p_h,    g_h);
    cudaGetSymbolAddress((void**)&p_q,    g_q);
    cudaGetSymbolAddress((void**)&p_k,    g_k);
    cudaGetSymbolAddress((void**)&p_v,    g_v);
    cudaGetSymbolAddress((void**)&p_ctx,  g_ctx);
    cudaGetSymbolAddress((void**)&p_gate, g_gate);
    cudaGetSymbolAddress((void**)&p_pb,   g_pb);

    // 1. LayerNorm
    ln_kernel<<<B_*T_, 256>>>(x, ln_w, ln_b, p_h);

    // 2. QKV projections (tf32 tensor-core NT GEMMs); q carries 64^-0.5
    dim3 g1(D_/128, (B_*T_)/128);
    sgemm_tf32<<<g1, 256>>>(p_h, wq, bq, nullptr, 0.125f, p_q, B_*T_, D_, D_);
    sgemm_tf32<<<g1, 256>>>(p_h, wk, bk, nullptr, 1.0f,   p_k, B_*T_, D_, D_);
    sgemm_tf32<<<g1, 256>>>(p_h, wv, bv, nullptr, 1.0f,   p_v, B_*T_, D_, D_);

    // 3. grep gate
    gate_kernel<<<(BH_*T_)/8, 256>>>(p_q, grep_w, grep_b, grep_a, p_gate);

    // 4. rel-position bias table + broadcast output
    pbtable_kernel<<<8, 256>>>(rel_e, p_pb);
    posbias_kernel<<<65536, 256>>>(p_pb, pos_out);

    // 5-7. fused attention (scores never hit HBM)
    flash_attn<<<dim3(T_/128, BH_), 256>>>(p_q, p_k, p_v, p_gate, p_pb, p_ctx);

    // 8. out = ctx @ wo^T + bo + x
    sgemm_tf32<<<g1, 256>>>(p_ctx, wo, bo, x, 1.0f, out, B_*T_, D_, D_);
}

// round 9
// speedup vs baseline: 2.8227x; 1.2862x over previous
#include <cuda_runtime.h>
#include <cuda_fp16.h>
#include <math.h>
#include <stdint.h>

#define B_ 4
#define T_ 1024
#define D_ 1024
#define H_ 16
#define HD_ 64
#define BH_ 64

// swizzle for fp16 GEMM smem: word row kk2 (k-pair index 0..7), col = m ^ VSW(kk2).
// Makes all fill stores AND all mma fragment loads bank-conflict-free.
#define VSW(kk2) ((((kk2) & 3) ^ ((kk2) >> 2)) << 3)

// ---------------- scratch (__device__ globals; no allocations allowed) -----
__device__ float g_h[B_*T_*D_];
__device__ float g_q[B_*T_*D_];
__device__ float g_k[B_*T_*D_];
__device__ float g_v[B_*T_*D_];
__device__ float g_ctx[B_*T_*D_];
__device__ float g_gate[BH_*T_];
__device__ float g_pb[H_*2048];

// ---------------- helpers ---------------------------------------------------
__device__ __forceinline__ float warp_sum(float v) {
    #pragma unroll
    for (int o = 16; o > 0; o >>= 1) v += __shfl_xor_sync(0xffffffffu, v, o);
    return v;
}
__device__ __forceinline__ void mma_fp16(float* c, const uint32_t* a, const uint32_t* b) {
    asm volatile(
        "mma.sync.aligned.m16n8k16.row.col.f32.f16.f16.f32 "
        "{%0,%1,%2,%3}, {%4,%5,%6,%7}, {%8,%9}, {%0,%1,%2,%3};\n"
        : "+f"(c[0]), "+f"(c[1]), "+f"(c[2]), "+f"(c[3])
        : "r"(a[0]), "r"(a[1]), "r"(a[2]), "r"(a[3]), "r"(b[0]), "r"(b[1]));
}
__device__ __forceinline__ uint32_t pkh2(float a, float b) {
    __half2 h = __floats2half2_rn(a, b);
    return *(uint32_t*)&h;
}

// ---------------- LayerNorm: one block per row ------------------------------
__global__ void ln_kernel(const float* __restrict__ x, const float* __restrict__ w,
                          const float* __restrict__ bb, float* __restrict__ out)
{
    int row = blockIdx.x, tid = threadIdx.x;
    const float4* xr = (const float4*)(x + (size_t)row * D_);
    float4 v = xr[tid];
    float s  = v.x + v.y + v.z + v.w;
    float s2 = v.x*v.x + v.y*v.y + v.z*v.z + v.w*v.w;
    __shared__ float sm1[8], sm2[8];
    __shared__ float mu_s, inv_s;
    s = warp_sum(s); s2 = warp_sum(s2);
    if ((tid & 31) == 0) { sm1[tid >> 5] = s; sm2[tid >> 5] = s2; }
    __syncthreads();
    if (tid == 0) {
        float ts = 0.f, ts2 = 0.f;
        #pragma unroll
        for (int i = 0; i < 8; i++) { ts += sm1[i]; ts2 += sm2[i]; }
        float mu = ts / (float)D_;
        float var = ts2 / (float)D_ - mu * mu;
        mu_s = mu; inv_s = rsqrtf(var + 1e-5f);
    }
    __syncthreads();
    float mu = mu_s, inv = inv_s;
    float4 wv = ((const float4*)w)[tid];
    float4 bv = ((const float4*)bb)[tid];
    float4 o;
    o.x = (v.x - mu) * inv * wv.x + bv.x;
    o.y = (v.y - mu) * inv * wv.y + bv.y;
    o.z = (v.z - mu) * inv * wv.z + bv.z;
    o.w = (v.w - mu) * inv * wv.w + bv.w;
    ((float4*)(out + (size_t)row * D_))[tid] = o;
}

// ---------------- fp16 tensor-core GEMM NT ----------------------------------
// C = alpha*(A·B^T + bias) [+ resid].  A: MxK rm, B: NxK rm. 128x128x16,
// 8 warps (2x4), warp tile 64x32 via mma.sync m16n8k16 f16, double-buffered.
// smem word layout: As[kk2][m ^ VSW(kk2)] holds halves (2*kk2, 2*kk2+1) of row m.
__global__ void __launch_bounds__(256, 2) sgemm_fp16(
    const float* __restrict__ A, const float* __restrict__ Bm,
    const float* __restrict__ bias, const float* __restrict__ resid,
    float alpha, float* __restrict__ C, int M, int N, int K)
{
    __shared__ uint32_t As[2][8][128];
    __shared__ uint32_t Bs[2][8][128];
    int tid = threadIdx.x;
    int bm = blockIdx.y * 128, bn = blockIdx.x * 128;
    int r0 = tid >> 2;              // 0..63
    int kc  = (tid & 3) * 4;        // float k-offset
    int kc2 = (tid & 3) * 2;        // half2 word row
    const float* Ap = A + (size_t)(bm + r0) * K + kc;
    const float* Bp = Bm + (size_t)(bn + r0) * K + kc;

    int warp = tid >> 5, lane = tid & 31;
    int mw = (warp >> 2) * 64;
    int nw = (warp & 3) * 32;
    int gr = lane >> 2, c4 = lane & 3;

    const int sv0 = VSW(kc2), sv1 = VSW(kc2 + 1);       // store swizzles
    const int v0 = VSW(c4), v1 = VSW(c4 + 4);           // load swizzles

    float acc[4][4][4];
    #pragma unroll
    for (int i = 0; i < 4; i++)
        #pragma unroll
        for (int j = 0; j < 4; j++)
            #pragma unroll
            for (int l = 0; l < 4; l++) acc[i][j][l] = 0.f;

    float4 ra0, ra1, rb0, rb1;

    // prologue: tile 0
    ra0 = *(const float4*)(Ap);
    ra1 = *(const float4*)(Ap + (size_t)64 * K);
    rb0 = *(const float4*)(Bp);
    rb1 = *(const float4*)(Bp + (size_t)64 * K);
    As[0][kc2    ][r0 ^ sv0]        = pkh2(ra0.x, ra0.y);
    As[0][kc2 + 1][r0 ^ sv1]        = pkh2(ra0.z, ra0.w);
    As[0][kc2    ][(r0 + 64) ^ sv0] = pkh2(ra1.x, ra1.y);
    As[0][kc2 + 1][(r0 + 64) ^ sv1] = pkh2(ra1.z, ra1.w);
    Bs[0][kc2    ][r0 ^ sv0]        = pkh2(rb0.x, rb0.y);
    Bs[0][kc2 + 1][r0 ^ sv1]        = pkh2(rb0.z, rb0.w);
    Bs[0][kc2    ][(r0 + 64) ^ sv0] = pkh2(rb1.x, rb1.y);
    Bs[0][kc2 + 1][(r0 + 64) ^ sv1] = pkh2(rb1.z, rb1.w);
    __syncthreads();

    int nkt = K >> 4;
    int buf = 0;
    for (int kt = 0; kt < nkt; ++kt) {
        if (kt + 1 < nkt) {
            const float* Ap2 = Ap + (kt + 1) * 16;
            const float* Bp2 = Bp + (kt + 1) * 16;
            ra0 = *(const float4*)(Ap2);
            ra1 = *(const float4*)(Ap2 + (size_t)64 * K);
            rb0 = *(const float4*)(Bp2);
            rb1 = *(const float4*)(Bp2 + (size_t)64 * K);
        }
        // one k16 mma block
        {
            uint32_t af[4][4], bfr[4][2];
            #pragma unroll
            for (int mi = 0; mi < 4; mi++) {
                int m = mw + mi * 16 + gr;
                af[mi][0] = As[buf][c4    ][m ^ v0];
                af[mi][1] = As[buf][c4    ][(m + 8) ^ v0];
                af[mi][2] = As[buf][c4 + 4][m ^ v1];
                af[mi][3] = As[buf][c4 + 4][(m + 8) ^ v1];
            }
            #pragma unroll
            for (int ni = 0; ni < 4; ni++) {
                int n = nw + ni * 8 + gr;
                bfr[ni][0] = Bs[buf][c4    ][n ^ v0];
                bfr[ni][1] = Bs[buf][c4 + 4][n ^ v1];
            }
            #pragma unroll
            for (int mi = 0; mi < 4; mi++)
                #pragma unroll
                for (int ni = 0; ni < 4; ni++)
                    mma_fp16(acc[mi][ni], af[mi], bfr[ni]);
        }
        if (kt + 1 < nkt) {
            buf ^= 1;
            As[buf][kc2    ][r0 ^ sv0]        = pkh2(ra0.x, ra0.y);
            As[buf][kc2 + 1][r0 ^ sv1]        = pkh2(ra0.z, ra0.w);
            As[buf][kc2    ][(r0 + 64) ^ sv0] = pkh2(ra1.x, ra1.y);
            As[buf][kc2 + 1][(r0 + 64) ^ sv1] = pkh2(ra1.z, ra1.w);
            Bs[buf][kc2    ][r0 ^ sv0]        = pkh2(rb0.x, rb0.y);
            Bs[buf][kc2 + 1][r0 ^ sv1]        = pkh2(rb0.z, rb0.w);
            Bs[buf][kc2    ][(r0 + 64) ^ sv0] = pkh2(rb1.x, rb1.y);
            Bs[buf][kc2 + 1][(r0 + 64) ^ sv1] = pkh2(rb1.z, rb1.w);
            __syncthreads();
        }
    }

    // epilogue
    #pragma unroll
    for (int ni = 0; ni < 4; ni++) {
        int ng = bn + nw + ni * 8 + c4 * 2;
        float2 b2 = *(const float2*)&bias[ng];
        #pragma unroll
        for (int mi = 0; mi < 4; mi++) {
            int mg = bm + mw + mi * 16 + gr;
            float2 lo, hi;
            lo.x = (acc[mi][ni][0] + b2.x) * alpha;
            lo.y = (acc[mi][ni][1] + b2.y) * alpha;
            hi.x = (acc[mi][ni][2] + b2.x) * alpha;
            hi.y = (acc[mi][ni][3] + b2.y) * alpha;
            if (resid) {
                float2 r1 = *(const float2*)&resid[(size_t)mg * N + ng];
                float2 r2 = *(const float2*)&resid[(size_t)(mg + 8) * N + ng];
                lo.x += r1.x; lo.y += r1.y;
                hi.x += r2.x; hi.y += r2.y;
            }
            *(float2*)&C[(size_t)mg * N + ng]       = lo;
            *(float2*)&C[(size_t)(mg + 8) * N + ng] = hi;
        }
    }
}

// ---------------- grep gate: one warp per (b,h,t) ---------------------------
__global__ void gate_kernel(const float* __restrict__ q, const float* __restrict__ gw,
                            const float* __restrict__ gb, const float* __restrict__ ga,
                            float* __restrict__ gate)
{
    __shared__ float sgw[8][64];
    int tid = threadIdx.x;
    ((float*)sgw)[tid]       = gw[tid];
    ((float*)sgw)[tid + 256] = gw[tid + 256];
    __syncthreads();
    int warp = tid >> 5, lane = tid & 31;
    size_t z = (size_t)blockIdx.x * 8 + warp;
    int t = (int)(z % T_);
    int h = (int)((z / T_) % H_);
    int b = (int)(z / ((size_t)H_ * T_));
    const float* qr = q + ((size_t)b * T_ + t) * D_ + h * HD_;
    float q0 = qr[lane] * 256.f;
    float q1 = qr[lane + 32] * 256.f;
    float y[8];
    #pragma unroll
    for (int j = 0; j < 8; j++)
        y[j] = q0 * sgw[j][lane] + q1 * sgw[j][lane + 32];
    #pragma unroll
    for (int o = 16; o > 0; o >>= 1)
        #pragma unroll
        for (int j = 0; j < 8; j++) y[j] += __shfl_xor_sync(0xffffffffu, y[j], o);
    if (lane == 0) {
        float s0 = y[0]+y[1]+y[2]+y[3] + gb[0]+gb[1]+gb[2]+gb[3];
        float s1 = y[4]+y[5]+y[6]+y[7] + gb[4]+gb[5]+gb[6]+gb[7];
        float ga_ = 1.f / (1.f + expf(-s0));
        float gbv = 1.f / (1.f + expf(-s1));
        gate[z] = ga_ * (gbv * ga[h] - 1.f) + 2.f;
    }
}

// ---------------- relative-position bias table: pb[h][rel+1023] -------------
__global__ void pbtable_kernel(const float* __restrict__ rel_emb, float* __restrict__ pb)
{
    int i = blockIdx.x * 256 + threadIdx.x;
    if (i >= 2048) return;
    if (i == 2047) {
        for (int h = 0; h < H_; h++) pb[h * 2048 + i] = 0.f;
        return;
    }
    int rel = i - 1023;
    int bucket = (rel > 0) ? 160 : 0;
    int n = abs(rel);
    int idx;
    if (n < 80) {
        idx = bucket + n;
    } else {
        double nf = (double)n;
        int large = 80 + (int)(log(nf / 80.0) / log(10.0) * 80.0);
        if (large > 159) large = 159;
        idx = bucket + large;
    }
    for (int h = 0; h < H_; h++) pb[h * 2048 + i] = rel_emb[idx * H_ + h];
}

// ---------------- pos_bias_out writer: (B*H, T, T) broadcast ----------------
__global__ void posbias_kernel(const float* __restrict__ pb, float* __restrict__ out)
{
    size_t gid = (size_t)blockIdx.x * 256 + threadIdx.x;
    int s4 = (int)(gid & 255);
    int t  = (int)((gid >> 8) & 1023);
    int bh = (int)(gid >> 18);
    int h  = bh & 15;
    const float* row = pb + h * 2048 + 1023 - t;
    int s = s4 * 4;
    float4 o = make_float4(row[s], row[s+1], row[s+2], row[s+3]);
    ((float4*)out)[gid] = o;
}

// ---------------- flash attention: QK^T + bias + online softmax + PV --------
// grid (T/128, BH), 256 threads (8 warps). Warp w owns t-rows [w*16, w*16+16).
// fp16 mma m16n8k16; KV tiles of 64; scores never leave the SM.
__global__ void __launch_bounds__(256) flash_attn(
    const float* __restrict__ q, const float* __restrict__ k,
    const float* __restrict__ v, const float* __restrict__ gate,
    const float* __restrict__ pb, float* __restrict__ ctx)
{
    int z = blockIdx.y;
    int b = z >> 4, h = z & 15;
    int bm = blockIdx.x * 128;
    const float* Qg = q + (size_t)b * T_ * D_ + h * HD_;
    const float* Kg = k + (size_t)b * T_ * D_ + h * HD_;
    const float* Vg = v + (size_t)b * T_ * D_ + h * HD_;
    float* Cg = ctx + (size_t)b * T_ * D_ + h * HD_;

    __shared__ __half ks[64][72];    // [key][dim]
    __shared__ __half vs[64][72];    // [dim][key]  (V^T)
    __shared__ __half ps[128][72];   // [t][s]
    __shared__ float gs[128];
    __shared__ float pbs[192];

    int tid = threadIdx.x;
    int w = tid >> 5, lane = tid & 31;
    int gr = lane >> 2, c4 = lane & 3;
    int trow = w * 16 + gr;

    if (tid < 128) gs[tid] = gate[(size_t)z * T_ + bm + tid];

    uint32_t qa[4][4];
    {
        const float* Q0 = Qg + (size_t)(bm + trow) * D_;
        const float* Q1 = Qg + (size_t)(bm + trow + 8) * D_;
        #pragma unroll
        for (int kb = 0; kb < 4; kb++) {
            int d0 = kb * 16 + 2 * c4;
            float2 f;
            f = *(const float2*)(Q0 + d0);     qa[kb][0] = pkh2(f.x, f.y);
            f = *(const float2*)(Q1 + d0);     qa[kb][1] = pkh2(f.x, f.y);
            f = *(const float2*)(Q0 + d0 + 8); qa[kb][2] = pkh2(f.x, f.y);
            f = *(const float2*)(Q1 + d0 + 8); qa[kb][3] = pkh2(f.x, f.y);
        }
    }

    float oacc[8][4];
    #pragma unroll
    for (int i = 0; i < 8; i++)
        #pragma unroll
        for (int j = 0; j < 4; j++) oacc[i][j] = 0.f;
    float m0 = -1e30f, m1 = -1e30f, l0 = 0.f, l1 = 0.f;

    for (int kv = 0; kv < 16; kv++) {
        __syncthreads();
        {
            int key = tid >> 2, d0 = (tid & 3) * 16;
            const float* Kr = Kg + (size_t)(kv * 64 + key) * D_ + d0;
            const float* Vr = Vg + (size_t)(kv * 64 + key) * D_ + d0;
            #pragma unroll
            for (int j = 0; j < 16; j += 4) {
                float4 kf = *(const float4*)(Kr + j);
                ks[key][d0 + j]     = __float2half_rn(kf.x);
                ks[key][d0 + j + 1] = __float2half_rn(kf.y);
                ks[key][d0 + j + 2] = __float2half_rn(kf.z);
                ks[key][d0 + j + 3] = __float2half_rn(kf.w);
                float4 vf = *(const float4*)(Vr + j);
                vs[d0 + j][key]     = __float2half_rn(vf.x);
                vs[d0 + j + 1][key] = __float2half_rn(vf.y);
                vs[d0 + j + 2][key] = __float2half_rn(vf.z);
                vs[d0 + j + 3][key] = __float2half_rn(vf.w);
            }
        }
        if (tid < 192) pbs[tid] = pb[h * 2048 + kv * 64 - bm + 896 + tid];
        __syncthreads();

        float sacc[8][4];
        #pragma unroll
        for (int i = 0; i < 8; i++)
            #pragma unroll
            for (int j = 0; j < 4; j++) sacc[i][j] = 0.f;
        #pragma unroll
        for (int kb = 0; kb < 4; kb++) {
            #pragma unroll
            for (int nb = 0; nb < 8; nb++) {
                uint32_t bf[2];
                bf[0] = *(const uint32_t*)&ks[nb * 8 + gr][kb * 16 + 2 * c4];
                bf[1] = *(const uint32_t*)&ks[nb * 8 + gr][kb * 16 + 2 * c4 + 8];
                mma_fp16(sacc[nb], qa[kb], bf);
            }
        }
        float g0 = gs[trow], g1 = gs[trow + 8];
        #pragma unroll
        for (int nb = 0; nb < 8; nb++) {
            int i0 = nb * 8 + 2 * c4 - trow + 127;
            sacc[nb][0] += g0 * pbs[i0];
            sacc[nb][1] += g0 * pbs[i0 + 1];
            sacc[nb][2] += g1 * pbs[i0 - 8];
            sacc[nb][3] += g1 * pbs[i0 - 7];
        }
        float mx0 = -1e30f, mx1 = -1e30f;
        #pragma unroll
        for (int nb = 0; nb < 8; nb++) {
            mx0 = fmaxf(mx0, fmaxf(sacc[nb][0], sacc[nb][1]));
            mx1 = fmaxf(mx1, fmaxf(sacc[nb][2], sacc[nb][3]));
        }
        mx0 = fmaxf(mx0, __shfl_xor_sync(0xffffffffu, mx0, 1));
        mx0 = fmaxf(mx0, __shfl_xor_sync(0xffffffffu, mx0, 2));
        mx1 = fmaxf(mx1, __shfl_xor_sync(0xffffffffu, mx1, 1));
        mx1 = fmaxf(mx1, __shfl_xor_sync(0xffffffffu, mx1, 2));
        float mn0 = fmaxf(m0, mx0), mn1 = fmaxf(m1, mx1);
        float c0 = __expf(m0 - mn0), c1 = __expf(m1 - mn1);
        float su0 = 0.f, su1 = 0.f;
        #pragma unroll
        for (int nb = 0; nb < 8; nb++) {
            float p0 = __expf(sacc[nb][0] - mn0);
            float p1 = __expf(sacc[nb][1] - mn0);
            float p2 = __expf(sacc[nb][2] - mn1);
            float p3 = __expf(sacc[nb][3] - mn1);
            su0 += p0 + p1; su1 += p2 + p3;
            *(uint32_t*)&ps[trow][nb * 8 + 2 * c4]     = pkh2(p0, p1);
            *(uint32_t*)&ps[trow + 8][nb * 8 + 2 * c4] = pkh2(p2, p3);
        }
        su0 += __shfl_xor_sync(0xffffffffu, su0, 1);
        su0 += __shfl_xor_sync(0xffffffffu, su0, 2);
        su1 += __shfl_xor_sync(0xffffffffu, su1, 1);
        su1 += __shfl_xor_sync(0xffffffffu, su1, 2);
        l0 = l0 * c0 + su0; l1 = l1 * c1 + su1;
        m0 = mn0; m1 = mn1;
        #pragma unroll
        for (int nb = 0; nb < 8; nb++) {
            oacc[nb][0] *= c0; oacc[nb][1] *= c0;
            oacc[nb][2] *= c1; oacc[nb][3] *= c1;
        }
        __syncwarp();

        #pragma unroll
        for (int sb = 0; sb < 4; sb++) {
            uint32_t pa[4];
            pa[0] = *(const uint32_t*)&ps[trow][sb * 16 + 2 * c4];
            pa[1] = *(const uint32_t*)&ps[trow + 8][sb * 16 + 2 * c4];
            pa[2] = *(const uint32_t*)&ps[trow][sb * 16 + 2 * c4 + 8];
            pa[3] = *(const uint32_t*)&ps[trow + 8][sb * 16 + 2 * c4 + 8];
            #pragma unroll
            for (int nb = 0; nb < 8; nb++) {
                uint32_t bf[2];
                bf[0] = *(const uint32_t*)&vs[nb * 8 + gr][sb * 16 + 2 * c4];
                bf[1] = *(const uint32_t*)&vs[nb * 8 + gr][sb * 16 + 2 * c4 + 8];
                mma_fp16(oacc[nb], pa, bf);
            }
        }
    }

    float inv0 = 1.f / l0, inv1 = 1.f / l1;
    #pragma unroll
    for (int nb = 0; nb < 8; nb++) {
        int d = nb * 8 + 2 * c4;
        *(float2*)&Cg[(size_t)(bm + trow) * D_ + d] =
            make_float2(oacc[nb][0] * inv0, oacc[nb][1] * inv0);
        *(float2*)&Cg[(size_t)(bm + trow + 8) * D_ + d] =
            make_float2(oacc[nb][2] * inv1, oacc[nb][3] * inv1);
    }
}

// ---------------- host launcher ---------------------------------------------
extern "C" void kernel_launch(void* const* d_in, const int* in_sizes, int n_in,
                              void* d_out, int out_size)
{
    const float* x      = (const float*)d_in[0];
    const float* ln_w   = (const float*)d_in[1];
    const float* ln_b   = (const float*)d_in[2];
    const float* wq     = (const float*)d_in[3];
    const float* bq     = (const float*)d_in[4];
    const float* wk     = (const float*)d_in[5];
    const float* bk     = (const float*)d_in[6];
    const float* wv     = (const float*)d_in[7];
    const float* bv     = (const float*)d_in[8];
    const float* wo     = (const float*)d_in[9];
    const float* bo     = (const float*)d_in[10];
    const float* rel_e  = (const float*)d_in[11];
    const float* grep_w = (const float*)d_in[12];
    const float* grep_b = (const float*)d_in[13];
    const float* grep_a = (const float*)d_in[14];

    float* out     = (float*)d_out;
    float* pos_out = out + (size_t)B_ * T_ * D_;

    float *p_h, *p_q, *p_k, *p_v, *p_ctx, *p_gate, *p_pb;
    cudaGetSymbolAddress((void**)&p_h,    g_h);
    cudaGetSymbolAddress((void**)&p_q,    g_q);
    cudaGetSymbolAddress((void**)&p_k,    g_k);
    cudaGetSymbolAddress((void**)&p_v,    g_v);
    cudaGetSymbolAddress((void**)&p_ctx,  g_ctx);
    cudaGetSymbolAddress((void**)&p_gate, g_gate);
    cudaGetSymbolAddress((void**)&p_pb,   g_pb);

    // 1. LayerNorm
    ln_kernel<<<B_*T_, 256>>>(x, ln_w, ln_b, p_h);

    // 2. QKV projections (fp16 tensor-core NT GEMMs); q carries 64^-0.5
    dim3 g1(D_/128, (B_*T_)/128);
    sgemm_fp16<<<g1, 256>>>(p_h, wq, bq, nullptr, 0.125f, p_q, B_*T_, D_, D_);
    sgemm_fp16<<<g1, 256>>>(p_h, wk, bk, nullptr, 1.0f,   p_k, B_*T_, D_, D_);
    sgemm_fp16<<<g1, 256>>>(p_h, wv, bv, nullptr, 1.0f,   p_v, B_*T_, D_, D_);

    // 3. grep gate
    gate_kernel<<<(BH_*T_)/8, 256>>>(p_q, grep_w, grep_b, grep_a, p_gate);

    // 4. rel-position bias table + broadcast output
    pbtable_kernel<<<8, 256>>>(rel_e, p_pb);
    posbias_kernel<<<65536, 256>>>(p_pb, pos_out);

    // 5-7. fused attention (scores never hit HBM)
    flash_attn<<<dim3(T_/128, BH_), 256>>>(p_q, p_k, p_v, p_gate, p_pb, p_ctx);

    // 8. out = ctx @ wo^T + bo + x
    sgemm_fp16<<<g1, 256>>>(p_ctx, wo, bo, x, 1.0f, out, B_*T_, D_, D_);
}

// round 10
// speedup vs baseline: 4.4317x; 1.5700x over previous
#include <cuda_runtime.h>
#include <cuda_fp16.h>
#include <math.h>
#include <stdint.h>

#define B_ 4
#define T_ 1024
#define D_ 1024
#define H_ 16
#define HD_ 64
#define BH_ 64

// ---------------- scratch (__device__ globals; no allocations allowed) -----
__device__ __half g_hh[B_*T_*D_];
__device__ __half g_qh[B_*T_*D_];
__device__ __half g_kh[B_*T_*D_];
__device__ __half g_vh[B_*T_*D_];
__device__ __half g_ctxh[B_*T_*D_];
__device__ __half g_wqh[D_*D_];
__device__ __half g_wkh[D_*D_];
__device__ __half g_wvh[D_*D_];
__device__ __half g_woh[D_*D_];
__device__ float g_gate[BH_*T_];
__device__ float g_pb[H_*2048];

// ---------------- helpers ---------------------------------------------------
__device__ __forceinline__ float warp_sum(float v) {
    #pragma unroll
    for (int o = 16; o > 0; o >>= 1) v += __shfl_xor_sync(0xffffffffu, v, o);
    return v;
}
__device__ __forceinline__ void mma_fp16(float* c, const uint32_t* a, const uint32_t* b) {
    asm volatile(
        "mma.sync.aligned.m16n8k16.row.col.f32.f16.f16.f32 "
        "{%0,%1,%2,%3}, {%4,%5,%6,%7}, {%8,%9}, {%0,%1,%2,%3};\n"
        : "+f"(c[0]), "+f"(c[1]), "+f"(c[2]), "+f"(c[3])
        : "r"(a[0]), "r"(a[1]), "r"(a[2]), "r"(a[3]), "r"(b[0]), "r"(b[1]));
}
__device__ __forceinline__ uint32_t pkh2(float a, float b) {
    __half2 h = __floats2half2_rn(a, b);
    return *(uint32_t*)&h;
}
__device__ __forceinline__ uint32_t smem_u32(const void* p) {
    return (uint32_t)__cvta_generic_to_shared(p);
}
__device__ __forceinline__ void cp16(uint32_t dst, const void* src) {
    asm volatile("cp.async.cg.shared.global [%0], [%1], 16;\n" :: "r"(dst), "l"(src));
}
#define CP_COMMIT() asm volatile("cp.async.commit_group;\n" ::)
#define CP_WAIT1()  asm volatile("cp.async.wait_group 1;\n" ::)
__device__ __forceinline__ void ldm_x4(uint32_t* r, uint32_t addr) {
    asm volatile("ldmatrix.sync.aligned.m8n8.x4.shared.b16 {%0,%1,%2,%3}, [%4];\n"
        : "=r"(r[0]), "=r"(r[1]), "=r"(r[2]), "=r"(r[3]) : "r"(addr));
}
__device__ __forceinline__ void ldm_x4_t(uint32_t* r, uint32_t addr) {
    asm volatile("ldmatrix.sync.aligned.m8n8.x4.trans.shared.b16 {%0,%1,%2,%3}, [%4];\n"
        : "=r"(r[0]), "=r"(r[1]), "=r"(r[2]), "=r"(r[3]) : "r"(addr));
}

// ---------------- f32 -> f16 bulk convert (weights) --------------------------
__global__ void f2h_kernel(const float* __restrict__ in, __half* __restrict__ out)
{
    int i = blockIdx.x * 256 + threadIdx.x;
    float4 v = ((const float4*)in)[i];
    ((uint32_t*)out)[2*i]     = pkh2(v.x, v.y);
    ((uint32_t*)out)[2*i + 1] = pkh2(v.z, v.w);
}

// ---------------- LayerNorm: one block per row, fp16 output ------------------
__global__ void ln_kernel(const float* __restrict__ x, const float* __restrict__ w,
                          const float* __restrict__ bb, __half* __restrict__ out)
{
    int row = blockIdx.x, tid = threadIdx.x;
    const float4* xr = (const float4*)(x + (size_t)row * D_);
    float4 v = xr[tid];
    float s  = v.x + v.y + v.z + v.w;
    float s2 = v.x*v.x + v.y*v.y + v.z*v.z + v.w*v.w;
    __shared__ float sm1[8], sm2[8];
    __shared__ float mu_s, inv_s;
    s = warp_sum(s); s2 = warp_sum(s2);
    if ((tid & 31) == 0) { sm1[tid >> 5] = s; sm2[tid >> 5] = s2; }
    __syncthreads();
    if (tid == 0) {
        float ts = 0.f, ts2 = 0.f;
        #pragma unroll
        for (int i = 0; i < 8; i++) { ts += sm1[i]; ts2 += sm2[i]; }
        float mu = ts / (float)D_;
        float var = ts2 / (float)D_ - mu * mu;
        mu_s = mu; inv_s = rsqrtf(var + 1e-5f);
    }
    __syncthreads();
    float mu = mu_s, inv = inv_s;
    float4 wv = ((const float4*)w)[tid];
    float4 bv = ((const float4*)bb)[tid];
    float ox = (v.x - mu) * inv * wv.x + bv.x;
    float oy = (v.y - mu) * inv * wv.y + bv.y;
    float oz = (v.z - mu) * inv * wv.z + bv.z;
    float ow = (v.w - mu) * inv * wv.w + bv.w;
    uint32_t* op = (uint32_t*)(out + (size_t)row * D_);
    op[tid*2]     = pkh2(ox, oy);
    op[tid*2 + 1] = pkh2(oz, ow);
}

// ---------------- fp16 GEMM NT: cp.async + ldmatrix --------------------------
// C = alpha*(A·B^T + bias) [+resid]. A: MxK fp16 rm, B: NxK fp16 rm.
// 128x128, BK=32, 3-stage cp.async, 8 warps 2x4 (warp tile 64x32).
// smem rows = 64 B (32 halves), SW64 swizzle: chunk ^= (row>>1)&3.
__global__ void __launch_bounds__(256, 2) hgemm(
    const __half* __restrict__ A, const __half* __restrict__ Bm,
    const float* __restrict__ bias, const float* __restrict__ resid,
    float alpha, float* __restrict__ Cf, __half* __restrict__ Ch,
    int M, int N, int K)
{
    __shared__ __half Ah[3][128*32];
    __shared__ __half Bh[3][128*32];
    int tid = threadIdx.x;
    int bm = blockIdx.y * 128, bn = blockIdx.x * 128;

    // fill mapping: thread t -> chunks t (rows 0-63) and t+256 (rows 64-127)
    int frow = tid >> 2;            // 0..63
    int fc16 = tid & 3;
    uint32_t fso = (uint32_t)frow * 64 + (uint32_t)((fc16 ^ ((frow >> 1) & 3)) << 4);
    const __half* ApG = A + (size_t)(bm + frow) * K + fc16 * 8;
    const __half* BpG = Bm + (size_t)(bn + frow) * K + fc16 * 8;
    uint32_t aBase[3], bBase[3];
    #pragma unroll
    for (int s = 0; s < 3; s++) { aBase[s] = smem_u32(Ah[s]); bBase[s] = smem_u32(Bh[s]); }

    int warp = tid >> 5, lane = tid & 31;
    int mw = (warp >> 2) * 64;
    int nw = (warp & 3) * 32;
    int gr = lane >> 2, c4 = lane & 3;
    int hi4  = lane >> 4;           // A chunk bit
    int bbit = (lane >> 3) & 1;     // B chunk bit

    // per-lane ldmatrix row bases
    uint32_t arow[4], aswz[4], brow[2], bswz[2];
    #pragma unroll
    for (int mi = 0; mi < 4; mi++) {
        arow[mi] = mw + mi * 16 + (lane & 15);
        aswz[mi] = (arow[mi] >> 1) & 3;
    }
    #pragma unroll
    for (int p = 0; p < 2; p++) {
        brow[p] = nw + p * 16 + (lane & 7) + ((lane >> 4) << 3);
        bswz[p] = (brow[p] >> 1) & 3;
    }

    float acc[4][4][4];
    #pragma unroll
    for (int i = 0; i < 4; i++)
        #pragma unroll
        for (int j = 0; j < 4; j++)
            #pragma unroll
            for (int l = 0; l < 4; l++) acc[i][j][l] = 0.f;

    int nkt = K >> 5;
    // prologue: stages 0 and 1
    #pragma unroll
    for (int s = 0; s < 2; s++) {
        cp16(aBase[s] + fso,            ApG + s * 32);
        cp16(aBase[s] + fso + 64 * 64,  ApG + (size_t)64 * K + s * 32);
        cp16(bBase[s] + fso,            BpG + s * 32);
        cp16(bBase[s] + fso + 64 * 64,  BpG + (size_t)64 * K + s * 32);
        CP_COMMIT();
    }
    CP_WAIT1();
    __syncthreads();

    for (int kt = 0; kt < nkt; ++kt) {
        int st = kt % 3;
        uint32_t aS = aBase[st], bS = bBase[st];
        #pragma unroll
        for (int kb = 0; kb < 2; kb++) {
            uint32_t af[4][4], bfr[4][2];
            uint32_t ac = 2 * kb + hi4;
            uint32_t bc = 2 * kb + bbit;
            #pragma unroll
            for (int mi = 0; mi < 4; mi++)
                ldm_x4(af[mi], aS + arow[mi] * 64 + (((ac ^ aswz[mi])) << 4));
            #pragma unroll
            for (int p = 0; p < 2; p++) {
                uint32_t r[4];
                ldm_x4(r, bS + brow[p] * 64 + (((bc ^ bswz[p])) << 4));
                bfr[2*p][0] = r[0]; bfr[2*p][1] = r[1];
                bfr[2*p+1][0] = r[2]; bfr[2*p+1][1] = r[3];
            }
            #pragma unroll
            for (int mi = 0; mi < 4; mi++)
                #pragma unroll
                for (int ni = 0; ni < 4; ni++)
                    mma_fp16(acc[mi][ni], af[mi], bfr[ni]);
        }
        if (kt + 2 < nkt) {
            int sn = (kt + 2) % 3;
            const __half* Ap2 = ApG + (kt + 2) * 32;
            const __half* Bp2 = BpG + (kt + 2) * 32;
            cp16(aBase[sn] + fso,           Ap2);
            cp16(aBase[sn] + fso + 64 * 64, Ap2 + (size_t)64 * K);
            cp16(bBase[sn] + fso,           Bp2);
            cp16(bBase[sn] + fso + 64 * 64, Bp2 + (size_t)64 * K);
        }
        CP_COMMIT();
        CP_WAIT1();
        __syncthreads();
    }

    // epilogue
    #pragma unroll
    for (int ni = 0; ni < 4; ni++) {
        int ng = bn + nw + ni * 8 + c4 * 2;
        float2 b2 = *(const float2*)&bias[ng];
        #pragma unroll
        for (int mi = 0; mi < 4; mi++) {
            int mg = bm + mw + mi * 16 + gr;
            float2 lo, hi;
            lo.x = (acc[mi][ni][0] + b2.x) * alpha;
            lo.y = (acc[mi][ni][1] + b2.y) * alpha;
            hi.x = (acc[mi][ni][2] + b2.x) * alpha;
            hi.y = (acc[mi][ni][3] + b2.y) * alpha;
            if (Ch) {
                *(uint32_t*)&Ch[(size_t)mg * N + ng]       = pkh2(lo.x, lo.y);
                *(uint32_t*)&Ch[(size_t)(mg + 8) * N + ng] = pkh2(hi.x, hi.y);
            } else {
                float2 r1 = *(const float2*)&resid[(size_t)mg * N + ng];
                float2 r2 = *(const float2*)&resid[(size_t)(mg + 8) * N + ng];
                lo.x += r1.x; lo.y += r1.y;
                hi.x += r2.x; hi.y += r2.y;
                *(float2*)&Cf[(size_t)mg * N + ng]       = lo;
                *(float2*)&Cf[(size_t)(mg + 8) * N + ng] = hi;
            }
        }
    }
}

// ---------------- grep gate: one warp per (b,h,t), fp16 q --------------------
__global__ void gate_kernel(const __half* __restrict__ q, const float* __restrict__ gw,
                            const float* __restrict__ gb, const float* __restrict__ ga,
                            float* __restrict__ gate)
{
    __shared__ float sgw[8][64];
    int tid = threadIdx.x;
    ((float*)sgw)[tid]       = gw[tid];
    ((float*)sgw)[tid + 256] = gw[tid + 256];
    __syncthreads();
    int warp = tid >> 5, lane = tid & 31;
    size_t z = (size_t)blockIdx.x * 8 + warp;
    int t = (int)(z % T_);
    int h = (int)((z / T_) % H_);
    int b = (int)(z / ((size_t)H_ * T_));
    const __half* qr = q + ((size_t)b * T_ + t) * D_ + h * HD_;
    float q0 = __half2float(qr[lane]) * 256.f;
    float q1 = __half2float(qr[lane + 32]) * 256.f;
    float y[8];
    #pragma unroll
    for (int j = 0; j < 8; j++)
        y[j] = q0 * sgw[j][lane] + q1 * sgw[j][lane + 32];
    #pragma unroll
    for (int o = 16; o > 0; o >>= 1)
        #pragma unroll
        for (int j = 0; j < 8; j++) y[j] += __shfl_xor_sync(0xffffffffu, y[j], o);
    if (lane == 0) {
        float s0 = y[0]+y[1]+y[2]+y[3] + gb[0]+gb[1]+gb[2]+gb[3];
        float s1 = y[4]+y[5]+y[6]+y[7] + gb[4]+gb[5]+gb[6]+gb[7];
        float ga_ = 1.f / (1.f + expf(-s0));
        float gbv = 1.f / (1.f + expf(-s1));
        gate[z] = ga_ * (gbv * ga[h] - 1.f) + 2.f;
    }
}

// ---------------- relative-position bias table: pb[h][rel+1023] -------------
__global__ void pbtable_kernel(const float* __restrict__ rel_emb, float* __restrict__ pb)
{
    int i = blockIdx.x * 256 + threadIdx.x;
    if (i >= 2048) return;
    if (i == 2047) {
        for (int h = 0; h < H_; h++) pb[h * 2048 + i] = 0.f;
        return;
    }
    int rel = i - 1023;
    int bucket = (rel > 0) ? 160 : 0;
    int n = abs(rel);
    int idx;
    if (n < 80) {
        idx = bucket + n;
    } else {
        double nf = (double)n;
        int large = 80 + (int)(log(nf / 80.0) / log(10.0) * 80.0);
        if (large > 159) large = 159;
        idx = bucket + large;
    }
    for (int h = 0; h < H_; h++) pb[h * 2048 + i] = rel_emb[idx * H_ + h];
}

// ---------------- pos_bias_out writer: (B*H, T, T) broadcast ----------------
__global__ void posbias_kernel(const float* __restrict__ pb, float* __restrict__ out)
{
    size_t gid = (size_t)blockIdx.x * 256 + threadIdx.x;
    int s4 = (int)(gid & 255);
    int t  = (int)((gid >> 8) & 1023);
    int bh = (int)(gid >> 18);
    int h  = bh & 15;
    const float* row = pb + h * 2048 + 1023 - t;
    int s = s4 * 4;
    float4 o = make_float4(row[s], row[s+1], row[s+2], row[s+3]);
    ((float4*)out)[gid] = o;
}

// ---------------- flash attention v2: fp16 io, cp.async, ldmatrix, reg-P ----
// grid (T/128, BH), 256 threads. Warp w owns t-rows [w*16, w*16+16).
// K/V tiles [64][64] fp16, SW128 swizzle, double-buffered cp.async.
__global__ void __launch_bounds__(256) flash_attn(
    const __half* __restrict__ q, const __half* __restrict__ k,
    const __half* __restrict__ v, const float* __restrict__ gate,
    const float* __restrict__ pb, __half* __restrict__ ctx)
{
    int z = blockIdx.y;
    int b = z >> 4, h = z & 15;
    int bm = blockIdx.x * 128;
    const __half* Qg = q + (size_t)b * T_ * D_ + h * HD_;
    const __half* Kg = k + (size_t)b * T_ * D_ + h * HD_;
    const __half* Vg = v + (size_t)b * T_ * D_ + h * HD_;
    __half* Cg = ctx + (size_t)b * T_ * D_ + h * HD_;

    __shared__ __half ks[2][64*64];
    __shared__ __half vs[2][64*64];
    __shared__ float pbs[2][192];
    __shared__ float gs[128];

    int tid = threadIdx.x;
    int w = tid >> 5, lane = tid & 31;
    int gr = lane >> 2, c4 = lane & 3;
    int trow = w * 16 + gr;

    uint32_t ksB[2] = { smem_u32(ks[0]), smem_u32(ks[1]) };
    uint32_t vsB[2] = { smem_u32(vs[0]), smem_u32(vs[1]) };

    // fill mapping: thread t -> chunk t (rows 0-31), chunk t+256 (rows 32-63)
    int frow = tid >> 3;            // 0..31
    int fc16 = tid & 7;
    uint32_t fso0 = (uint32_t)frow * 128 + (uint32_t)((fc16 ^ (frow & 7)) << 4);
    uint32_t fso1 = (uint32_t)(frow + 32) * 128 + (uint32_t)((fc16 ^ ((frow + 32) & 7)) << 4);
    const __half* KpG = Kg + (size_t)frow * D_ + fc16 * 8;
    const __half* VpG = Vg + (size_t)frow * D_ + fc16 * 8;

    if (tid < 128) gs[tid] = gate[(size_t)z * T_ + bm + tid];
    if (tid < 192) {
        pbs[0][tid] = pb[h * 2048 + 0 * 64 - bm + 896 + tid];
        pbs[1][tid] = pb[h * 2048 + 1 * 64 - bm + 896 + tid];
    }
    // prologue: tiles 0 and 1
    #pragma unroll
    for (int s = 0; s < 2; s++) {
        size_t go = (size_t)s * 64 * D_;
        cp16(ksB[s] + fso0, KpG + go);
        cp16(ksB[s] + fso1, KpG + go + (size_t)32 * D_);
        cp16(vsB[s] + fso0, VpG + go);
        cp16(vsB[s] + fso1, VpG + go + (size_t)32 * D_);
        CP_COMMIT();
    }

    // Q fragments: direct fp16 gmem loads
    uint32_t qa[4][4];
    {
        const uint32_t* Q0 = (const uint32_t*)(Qg + (size_t)(bm + trow) * D_);
        const uint32_t* Q1 = (const uint32_t*)(Qg + (size_t)(bm + trow + 8) * D_);
        #pragma unroll
        for (int kb = 0; kb < 4; kb++) {
            int wv0 = kb * 8 + c4;          // uint32 index = halves/2
            qa[kb][0] = Q0[wv0];
            qa[kb][1] = Q1[wv0];
            qa[kb][2] = Q0[wv0 + 4];
            qa[kb][3] = Q1[wv0 + 4];
        }
    }

    // ldmatrix lane bases
    uint32_t krow[4], vrowb;
    #pragma unroll
    for (int p = 0; p < 4; p++)
        krow[p] = p * 16 + (lane & 7) + ((lane >> 4) << 3);
    vrowb = (lane & 7) + (((lane >> 3) & 1) << 3);
    int bbit = (lane >> 3) & 1;
    int hi4 = lane >> 4;

    float oacc[8][4];
    #pragma unroll
    for (int i = 0; i < 8; i++)
        #pragma unroll
        for (int j = 0; j < 4; j++) oacc[i][j] = 0.f;
    float m0 = -1e30f, m1 = -1e30f, l0 = 0.f, l1 = 0.f;

    CP_WAIT1();
    __syncthreads();

    int buf = 0;
    for (int kv = 0; kv < 16; kv++) {
        // S = Q K^T  (128 x 64)
        float sacc[8][4];
        #pragma unroll
        for (int i = 0; i < 8; i++)
            #pragma unroll
            for (int j = 0; j < 4; j++) sacc[i][j] = 0.f;
        uint32_t kS = ksB[buf];
        #pragma unroll
        for (int kb = 0; kb < 4; kb++) {
            uint32_t kc = 2 * kb + bbit;
            #pragma unroll
            for (int p = 0; p < 4; p++) {
                uint32_t r[4];
                ldm_x4(r, kS + krow[p] * 128 + (((kc ^ (krow[p] & 7))) << 4));
                uint32_t bf0[2] = { r[0], r[1] };
                uint32_t bf1[2] = { r[2], r[3] };
                mma_fp16(sacc[2*p],     qa[kb], bf0);
                mma_fp16(sacc[2*p + 1], qa[kb], bf1);
            }
        }
        // + gate[t] * pb[s - t]
        float g0 = gs[trow], g1 = gs[trow + 8];
        const float* pbc = pbs[buf];
        #pragma unroll
        for (int nb = 0; nb < 8; nb++) {
            int i0 = nb * 8 + 2 * c4 - trow + 127;
            sacc[nb][0] += g0 * pbc[i0];
            sacc[nb][1] += g0 * pbc[i0 + 1];
            sacc[nb][2] += g1 * pbc[i0 - 8];
            sacc[nb][3] += g1 * pbc[i0 - 7];
        }
        // online softmax
        float mx0 = -1e30f, mx1 = -1e30f;
        #pragma unroll
        for (int nb = 0; nb < 8; nb++) {
            mx0 = fmaxf(mx0, fmaxf(sacc[nb][0], sacc[nb][1]));
            mx1 = fmaxf(mx1, fmaxf(sacc[nb][2], sacc[nb][3]));
        }
        mx0 = fmaxf(mx0, __shfl_xor_sync(0xffffffffu, mx0, 1));
        mx0 = fmaxf(mx0, __shfl_xor_sync(0xffffffffu, mx0, 2));
        mx1 = fmaxf(mx1, __shfl_xor_sync(0xffffffffu, mx1, 1));
        mx1 = fmaxf(mx1, __shfl_xor_sync(0xffffffffu, mx1, 2));
        float mn0 = fmaxf(m0, mx0), mn1 = fmaxf(m1, mx1);
        float c0 = __expf(m0 - mn0), c1 = __expf(m1 - mn1);
        float su0 = 0.f, su1 = 0.f;
        #pragma unroll
        for (int nb = 0; nb < 8; nb++) {
            sacc[nb][0] = __expf(sacc[nb][0] - mn0);
            sacc[nb][1] = __expf(sacc[nb][1] - mn0);
            sacc[nb][2] = __expf(sacc[nb][2] - mn1);
            sacc[nb][3] = __expf(sacc[nb][3] - mn1);
            su0 += sacc[nb][0] + sacc[nb][1];
            su1 += sacc[nb][2] + sacc[nb][3];
        }
        su0 += __shfl_xor_sync(0xffffffffu, su0, 1);
        su0 += __shfl_xor_sync(0xffffffffu, su0, 2);
        su1 += __shfl_xor_sync(0xffffffffu, su1, 1);
        su1 += __shfl_xor_sync(0xffffffffu, su1, 2);
        l0 = l0 * c0 + su0; l1 = l1 * c1 + su1;
        m0 = mn0; m1 = mn1;
        #pragma unroll
        for (int nb = 0; nb < 8; nb++) {
            oacc[nb][0] *= c0; oacc[nb][1] *= c0;
            oacc[nb][2] *= c1; oacc[nb][3] *= c1;
        }
        // O += P V  — P fragments come straight from sacc registers
        uint32_t vS = vsB[buf];
        #pragma unroll
        for (int sb = 0; sb < 4; sb++) {
            uint32_t pa[4];
            pa[0] = pkh2(sacc[2*sb][0],     sacc[2*sb][1]);
            pa[1] = pkh2(sacc[2*sb][2],     sacc[2*sb][3]);
            pa[2] = pkh2(sacc[2*sb + 1][0], sacc[2*sb + 1][1]);
            pa[3] = pkh2(sacc[2*sb + 1][2], sacc[2*sb + 1][3]);
            uint32_t vrow = sb * 16 + vrowb;
            uint32_t vswz = vrow & 7;
            #pragma unroll
            for (int p = 0; p < 4; p++) {
                uint32_t vc = 2 * p + hi4;
                uint32_t r[4];
                ldm_x4_t(r, vS + vrow * 128 + (((vc ^ vswz)) << 4));
                uint32_t bf0[2] = { r[0], r[1] };
                uint32_t bf1[2] = { r[2], r[3] };
                mma_fp16(oacc[2*p],     pa, bf0);
                mma_fp16(oacc[2*p + 1], pa, bf1);
            }
        }

        __syncthreads();    // all warps done with buf before refill
        if (kv + 2 < 16) {
            size_t go = (size_t)(kv + 2) * 64 * D_;
            cp16(ksB[buf] + fso0, KpG + go);
            cp16(ksB[buf] + fso1, KpG + go + (size_t)32 * D_);
            cp16(vsB[buf] + fso0, VpG + go);
            cp16(vsB[buf] + fso1, VpG + go + (size_t)32 * D_);
            if (tid < 192)
                pbs[buf][tid] = pb[h * 2048 + (kv + 2) * 64 - bm + 896 + tid];
        }
        CP_COMMIT();
        CP_WAIT1();
        __syncthreads();
        buf ^= 1;
    }

    // epilogue: O / l  ->  ctx (fp16)
    float inv0 = 1.f / l0, inv1 = 1.f / l1;
    #pragma unroll
    for (int nb = 0; nb < 8; nb++) {
        int d = nb * 8 + 2 * c4;
        *(uint32_t*)&Cg[(size_t)(bm + trow) * D_ + d] =
            pkh2(oacc[nb][0] * inv0, oacc[nb][1] * inv0);
        *(uint32_t*)&Cg[(size_t)(bm + trow + 8) * D_ + d] =
            pkh2(oacc[nb][2] * inv1, oacc[nb][3] * inv1);
    }
}

// ---------------- host launcher ---------------------------------------------
extern "C" void kernel_launch(void* const* d_in, const int* in_sizes, int n_in,
                              void* d_out, int out_size)
{
    const float* x      = (const float*)d_in[0];
    const float* ln_w   = (const float*)d_in[1];
    const float* ln_b   = (const float*)d_in[2];
    const float* wq     = (const float*)d_in[3];
    const float* bq     = (const float*)d_in[4];
    const float* wk     = (const float*)d_in[5];
    const float* bk     = (const float*)d_in[6];
    const float* wv     = (const float*)d_in[7];
    const float* bv     = (const float*)d_in[8];
    const float* wo     = (const float*)d_in[9];
    const float* bo     = (const float*)d_in[10];
    const float* rel_e  = (const float*)d_in[11];
    const float* grep_w = (const float*)d_in[12];
    const float* grep_b = (const float*)d_in[13];
    const float* grep_a = (const float*)d_in[14];

    float* out     = (float*)d_out;
    float* pos_out = out + (size_t)B_ * T_ * D_;

    __half *p_hh, *p_qh, *p_kh, *p_vh, *p_ctxh, *p_wqh, *p_wkh, *p_wvh, *p_woh;
    float *p_gate, *p_pb;
    cudaGetSymbolAddress((void**)&p_hh,   g_hh);
    cudaGetSymbolAddress((void**)&p_qh,   g_qh);
    cudaGetSymbolAddress((void**)&p_kh,   g_kh);
    cudaGetSymbolAddress((void**)&p_vh,   g_vh);
    cudaGetSymbolAddress((void**)&p_ctxh, g_ctxh);
    cudaGetSymbolAddress((void**)&p_wqh,  g_wqh);
    cudaGetSymbolAddress((void**)&p_wkh,  g_wkh);
    cudaGetSymbolAddress((void**)&p_wvh,  g_wvh);
    cudaGetSymbolAddress((void**)&p_woh,  g_woh);
    cudaGetSymbolAddress((void**)&p_gate, g_gate);
    cudaGetSymbolAddress((void**)&p_pb,   g_pb);

    // 0. fp16 conversions (weights) + LayerNorm (writes fp16 h)
    int wblk = (D_ * D_) / (256 * 4);
    f2h_kernel<<<wblk, 256>>>(wq, p_wqh);
    f2h_kernel<<<wblk, 256>>>(wk, p_wkh);
    f2h_kernel<<<wblk, 256>>>(wv, p_wvh);
    f2h_kernel<<<wblk, 256>>>(wo, p_woh);
    ln_kernel<<<B_*T_, 256>>>(x, ln_w, ln_b, p_hh);

    // 2. QKV projections (fp16 in, fp16 out); q carries scaling 64^-0.5
    dim3 g1(D_/128, (B_*T_)/128);
    hgemm<<<g1, 256>>>(p_hh, p_wqh, bq, nullptr, 0.125f, nullptr, p_qh, B_*T_, D_, D_);
    hgemm<<<g1, 256>>>(p_hh, p_wkh, bk, nullptr, 1.0f,   nullptr, p_kh, B_*T_, D_, D_);
    hgemm<<<g1, 256>>>(p_hh, p_wvh, bv, nullptr, 1.0f,   nullptr, p_vh, B_*T_, D_, D_);

    // 3. grep gate
    gate_kernel<<<(BH_*T_)/8, 256>>>(p_qh, grep_w, grep_b, grep_a, p_gate);

    // 4. rel-position bias table + broadcast output
    pbtable_kernel<<<8, 256>>>(rel_e, p_pb);
    posbias_kernel<<<65536, 256>>>(p_pb, pos_out);

    // 5-7. fused attention (fp16 io, scores never hit HBM)
    flash_attn<<<dim3(T_/128, BH_), 256>>>(p_qh, p_kh, p_vh, p_gate, p_pb, p_ctxh);

    // 8. out = ctx @ wo^T + bo + x  (fp32 out + residual)
    hgemm<<<g1, 256>>>(p_ctxh, p_woh, bo, x, 1.0f, out, nullptr, B_*T_, D_, D_);
}